// round 1
// baseline (speedup 1.0000x reference)
#include <cuda_runtime.h>
#include <math.h>

#define BATCH 256
#define NODE  512
#define WIN   64
#define EMB   64
#define TOPK  16
#define INTER 512
#define NT    (BATCH*NODE)     /* 131072 */
#define NEG   0.2f
#define EPS   1e-5f

// ---------------- scratch (static device globals; no runtime allocation) ----------------
__device__ float g_xl[NT*EMB];
__device__ float g_agg[NT*EMB];
__device__ float g_z[NT*EMB];
__device__ float g_zr[NT*EMB];
__device__ float g_si[NT];
__device__ float g_sj[NT];
__device__ int   g_topk[NODE*TOPK];
__device__ float g_ei[NODE], g_ej[NODE], g_inv[NODE];
// [0:64]=bn1 sum  [64:128]=bn1 sq  [128:192]=bn2 sum [192:256]=bn2 sq
// [256:320]=zr colsum  [320:4416]=M2 (64x64 second moment of zr)
__device__ float g_stats[4416];
__device__ float g_sc1[EMB], g_sh1[EMB], g_sc2[EMB], g_sh2[EMB];
__device__ float g_s3[INTER], g_t3[INTER];

// ---------------- prep: zero stats; per-node embedding dots + inv norms ----------------
__global__ void k_prep(const float* __restrict__ W_emb,
                       const float* __restrict__ aei,
                       const float* __restrict__ aej) {
    int t = threadIdx.x;
    if (blockIdx.x == 0) {
        for (int i = t; i < 4416; i += blockDim.x) g_stats[i] = 0.f;
    } else {
        int v = t;  // 512 threads
        const float* w = W_emb + v*EMB;
        float di = 0.f, dj = 0.f, nn = 0.f;
        #pragma unroll
        for (int k = 0; k < EMB; k++) {
            float x = w[k];
            di += x*aei[k]; dj += x*aej[k]; nn += x*x;
        }
        g_ei[v] = di; g_ej[v] = dj; g_inv[v] = rsqrtf(nn);
    }
}

// ---------------- cosine-similarity top-k (one block per node) ----------------
__global__ void k_topk(const float* __restrict__ W_emb) {
    __shared__ float wi[64];
    __shared__ float cosv[NODE];
    __shared__ float rv[128];
    __shared__ int   ri[128];
    int i = blockIdx.x, t = threadIdx.x;
    if (t < 64) wi[t] = W_emb[i*64 + t];
    __syncthreads();
    float inv_i = g_inv[i];
    for (int j = t; j < NODE; j += 128) {
        const float4* wj = (const float4*)&W_emb[j*64];
        float d = 0.f;
        #pragma unroll
        for (int kk = 0; kk < 16; kk++) {
            float4 b = wj[kk];
            d += wi[kk*4+0]*b.x + wi[kk*4+1]*b.y + wi[kk*4+2]*b.z + wi[kk*4+3]*b.w;
        }
        cosv[j] = d * inv_i * g_inv[j];
    }
    __syncthreads();
    for (int s = 0; s < TOPK; s++) {
        float bv = -3e38f; int bi = NODE;
        for (int j = t; j < NODE; j += 128) {
            float v = cosv[j];
            if (v > bv || (v == bv && j < bi)) { bv = v; bi = j; }
        }
        rv[t] = bv; ri[t] = bi;
        __syncthreads();
        for (int off = 64; off > 0; off >>= 1) {
            if (t < off) {
                float v2 = rv[t+off]; int i2 = ri[t+off];
                if (v2 > rv[t] || (v2 == rv[t] && i2 < ri[t])) { rv[t] = v2; ri[t] = i2; }
            }
            __syncthreads();
        }
        if (t == 0) { g_topk[i*TOPK + s] = ri[0]; cosv[ri[0]] = -3e38f; }
        __syncthreads();
    }
}

// ---------------- xl = x @ W_lin^T  fused with attention scores s_i, s_j ----------------
__global__ void k_xl(const float* __restrict__ x, const float* __restrict__ W_lin,
                     const float* __restrict__ att_i, const float* __restrict__ att_j) {
    __shared__ float As[64*68];   // As[k][r] = x[row0+r][k]
    __shared__ float Bs[64*68];   // Bs[k][e] = W_lin[e][k]
    __shared__ float sred[128];
    __shared__ float ai[64], aj[64];
    int t = threadIdx.x;
    int row0 = blockIdx.x * 64;
    if (t < 64) { ai[t] = att_i[t]; aj[t] = att_j[t]; }
    if (t < 128) sred[t] = 0.f;
    for (int i = t; i < 4096; i += 256) {
        int r = i >> 6, k = i & 63;
        As[k*68 + r] = x[row0*64 + i];
        Bs[k*68 + r] = W_lin[i];   // r == e here
    }
    __syncthreads();
    int tx = t & 15, ty = t >> 4;
    float acc[4][4];
    #pragma unroll
    for (int r = 0; r < 4; r++)
        #pragma unroll
        for (int c = 0; c < 4; c++) acc[r][c] = 0.f;
    #pragma unroll 4
    for (int k = 0; k < 64; k++) {
        float4 a = *(const float4*)&As[k*68 + ty*4];
        float4 b = *(const float4*)&Bs[k*68 + tx*4];
        float ar[4] = {a.x, a.y, a.z, a.w};
        float br[4] = {b.x, b.y, b.z, b.w};
        #pragma unroll
        for (int r = 0; r < 4; r++)
            #pragma unroll
            for (int c = 0; c < 4; c++) acc[r][c] += ar[r]*br[c];
    }
    float pi[4] = {0,0,0,0}, pj[4] = {0,0,0,0};
    #pragma unroll
    for (int r = 0; r < 4; r++) {
        float4 o = make_float4(acc[r][0], acc[r][1], acc[r][2], acc[r][3]);
        *(float4*)&g_xl[(row0 + ty*4 + r)*64 + tx*4] = o;
        #pragma unroll
        for (int c = 0; c < 4; c++) {
            pi[r] += acc[r][c]*ai[tx*4+c];
            pj[r] += acc[r][c]*aj[tx*4+c];
        }
    }
    #pragma unroll
    for (int r = 0; r < 4; r++) {
        atomicAdd(&sred[ty*4 + r], pi[r]);
        atomicAdd(&sred[64 + ty*4 + r], pj[r]);
    }
    __syncthreads();
    if (t < 64) {
        int n = row0 + t, v = n & (NODE-1);
        g_si[n] = sred[t]      + g_ei[v];
        g_sj[n] = sred[64 + t] + g_ej[v];
    }
}

// ---------------- GAT aggregation (warp per node; softmax over 16 nbrs) + bn1 stats ----------------
__global__ void k_agg(const float* __restrict__ b_gnn) {
    __shared__ int   tk[64*16];
    __shared__ float sm_s[64], sm_q[64];
    int t = threadIdx.x, warp = t >> 5, lane = t & 31;
    int n0 = blockIdx.x * 64;
    int v0 = n0 & (NODE-1);
    int batchBase = n0 - v0;
    for (int i = t; i < 64*16; i += 256) tk[i] = g_topk[v0*TOPK + i];
    if (t < 64) { sm_s[t] = 0.f; sm_q[t] = 0.f; }
    __syncthreads();
    int k = lane & 15;
    int c0 = lane*2;
    float bg0 = b_gnn[c0], bg1 = b_gnn[c0+1];
    float s0=0,q0=0,s1=0,q1=0;
    for (int nl = warp; nl < 64; nl += 8) {
        int n = n0 + nl;
        int nbr = batchBase + tk[nl*16 + k];
        float a = g_si[n] + g_sj[nbr];
        a = a > 0.f ? a : NEG*a;
        float m = a;
        #pragma unroll
        for (int o = 8; o > 0; o >>= 1) m = fmaxf(m, __shfl_xor_sync(0xffffffffu, m, o, 16));
        float ex = expf(a - m);
        float den = ex;
        #pragma unroll
        for (int o = 8; o > 0; o >>= 1) den += __shfl_xor_sync(0xffffffffu, den, o, 16);
        float w = ex / den;
        float ax = 0.f, ay = 0.f;
        #pragma unroll
        for (int kk = 0; kk < 16; kk++) {
            float wk = __shfl_sync(0xffffffffu, w,   kk, 16);
            int   nb = __shfl_sync(0xffffffffu, nbr, kk, 16);
            float2 vv = *(const float2*)&g_xl[nb*EMB + c0];
            ax += wk*vv.x; ay += wk*vv.y;
        }
        *(float2*)&g_agg[n*EMB + c0] = make_float2(ax, ay);
        float z0 = ax + bg0, z1 = ay + bg1;
        s0 += z0; q0 += z0*z0; s1 += z1; q1 += z1*z1;
    }
    atomicAdd(&sm_s[c0],   s0); atomicAdd(&sm_q[c0],   q0);
    atomicAdd(&sm_s[c0+1], s1); atomicAdd(&sm_q[c0+1], q1);
    __syncthreads();
    if (t < 64) { atomicAdd(&g_stats[t], sm_s[t]); atomicAdd(&g_stats[64+t], sm_q[t]); }
}

// ---------------- finalize bn1/bn2 scale+shift ----------------
__global__ void k_bnfin(const float* __restrict__ gamma, const float* __restrict__ beta, int which) {
    int c = threadIdx.x;
    if (c >= EMB) return;
    float s = g_stats[which*128 + c], q = g_stats[which*128 + 64 + c];
    float m = s * (1.f/NT);
    float v = q * (1.f/NT) - m*m;
    float sc = gamma[c] * rsqrtf(v + EPS);
    float sh = beta[c] - m*sc;
    if (which == 0) { g_sc1[c] = sc; g_sh1[c] = sh; }
    else            { g_sc2[c] = sc; g_sh2[c] = sh; }
}

// ---------------- h = relu(bn1(agg+b)); z = h * W_emb ; bn2 stats ----------------
__global__ void k_hz(const float* __restrict__ b_gnn, const float* __restrict__ W_emb) {
    __shared__ float sm_s[64], sm_q[64];
    int t = threadIdx.x;
    if (t < 64) { sm_s[t] = 0.f; sm_q[t] = 0.f; }
    __syncthreads();
    int gt = blockIdx.x*256 + t;
    int cp = gt & 31;
    int c0 = cp*2;
    float sc0 = g_sc1[c0], sc1v = g_sc1[c0+1];
    float sh0 = g_sh1[c0], sh1v = g_sh1[c0+1];
    float bg0 = b_gnn[c0], bg1 = b_gnn[c0+1];
    float s0=0,q0=0,s1=0,q1=0;
    const float2* a2 = (const float2*)g_agg;
    float2* z2 = (float2*)g_z;
    const int stride = 1024*256;
    for (int idx = gt; idx < NT*32; idx += stride) {
        int row = idx >> 5;
        int v = row & (NODE-1);
        float2 a = a2[idx];
        float h0 = fmaxf((a.x + bg0)*sc0 + sh0, 0.f);
        float h1 = fmaxf((a.y + bg1)*sc1v + sh1v, 0.f);
        float2 we = *(const float2*)&W_emb[v*EMB + c0];
        float z0 = h0 * we.x;
        float z1 = h1 * we.y;
        z2[idx] = make_float2(z0, z1);
        s0 += z0; q0 += z0*z0; s1 += z1; q1 += z1*z1;
    }
    atomicAdd(&sm_s[c0],   s0); atomicAdd(&sm_q[c0],   q0);
    atomicAdd(&sm_s[c0+1], s1); atomicAdd(&sm_q[c0+1], q1);
    __syncthreads();
    if (t < 64) { atomicAdd(&g_stats[128+t], sm_s[t]); atomicAdd(&g_stats[192+t], sm_q[t]); }
}

// ---------------- zr = relu(bn2(z)) ; SYRK: M2 += zr^T zr ; colsum ----------------
__global__ void k_zr() {
    __shared__ float zs[128*68];
    __shared__ float ssc[64], ssh[64];
    int t = threadIdx.x;
    if (t < 64) { ssc[t] = g_sc2[t]; ssh[t] = g_sh2[t]; }
    __syncthreads();
    int row0 = blockIdx.x * 128;
    for (int i = t; i < 128*64; i += 256) {
        int r = i >> 6, c = i & 63;
        float val = g_z[row0*64 + i];
        float zv = fmaxf(val*ssc[c] + ssh[c], 0.f);
        g_zr[row0*64 + i] = zv;
        zs[r*68 + c] = zv;
    }
    __syncthreads();
    if (t < 64) {
        float s = 0.f;
        for (int r = 0; r < 128; r++) s += zs[r*68 + t];
        atomicAdd(&g_stats[256 + t], s);
    }
    int tx = t & 15, ty = t >> 4;
    int a0 = ty*4, b0 = tx*4;
    float acc[4][4];
    #pragma unroll
    for (int i = 0; i < 4; i++)
        #pragma unroll
        for (int j = 0; j < 4; j++) acc[i][j] = 0.f;
    #pragma unroll 4
    for (int r = 0; r < 128; r++) {
        float4 va = *(const float4*)&zs[r*68 + a0];
        float4 vb = *(const float4*)&zs[r*68 + b0];
        float av[4] = {va.x, va.y, va.z, va.w};
        float bv[4] = {vb.x, vb.y, vb.z, vb.w};
        #pragma unroll
        for (int i = 0; i < 4; i++)
            #pragma unroll
            for (int j = 0; j < 4; j++) acc[i][j] += av[i]*bv[j];
    }
    #pragma unroll
    for (int i = 0; i < 4; i++)
        #pragma unroll
        for (int j = 0; j < 4; j++)
            atomicAdd(&g_stats[320 + (a0+i)*64 + b0 + j], acc[i][j]);
}

// ---------------- analytic BN3 params: mean/var of y=zr@W1^T+b1 from (zbar, Cov) ----------------
__global__ void k_bn3fin(const float* __restrict__ W1, const float* __restrict__ b1,
                         const float* __restrict__ g3, const float* __restrict__ b3) {
    __shared__ float Cov[EMB*EMB];
    __shared__ float zb[EMB];
    int t = threadIdx.x;
    for (int i = t; i < EMB; i += 32) zb[i] = g_stats[256+i] * (1.f/NT);
    __syncthreads();
    for (int i = t; i < EMB*EMB; i += 32)
        Cov[i] = g_stats[320+i] * (1.f/NT) - zb[i >> 6]*zb[i & 63];
    __syncthreads();
    int c = blockIdx.x*32 + t;
    const float* wc = W1 + c*EMB;
    float wr[EMB];
    #pragma unroll
    for (int k = 0; k < EMB; k++) wr[k] = wc[k];
    float m = b1[c];
    #pragma unroll
    for (int k = 0; k < EMB; k++) m += zb[k]*wr[k];
    float var = 0.f;
    for (int a = 0; a < EMB; a++) {
        float ta = 0.f;
        #pragma unroll 8
        for (int b = 0; b < EMB; b++) ta += Cov[a*EMB + b]*wr[b];
        var += ta * wr[a];
    }
    float sc = g3[c] * rsqrtf(var + EPS);
    g_s3[c] = sc;
    g_t3[c] = b3[c] - m*sc;
}

// ---------------- final fused GEMM: out = relu(bn3(zr@W1^T)) @ W2^T + b2 ----------------
#define W1T_PITCH 516
#define ZRT_PITCH 36
#define SMEM_FINAL ((64*W1T_PITCH + 64*ZRT_PITCH + 3*INTER + 32)*4)

__global__ void __launch_bounds__(256, 1)
k_final(const float* __restrict__ W1, const float* __restrict__ W2,
        const float* __restrict__ b2, float* __restrict__ out) {
    extern __shared__ float sm[];
    float* W1t  = sm;                        // [64][516] : W1t[k][c]
    float* zrt  = W1t + 64*W1T_PITCH;        // [64][36]  : zrt[k][r]
    float* ss3  = zrt + 64*ZRT_PITCH;        // [512]
    float* st3  = ss3 + INTER;               // [512]
    float* sw2  = st3 + INTER;               // [512]
    float* outp = sw2 + INTER;               // [32]
    int t = threadIdx.x;
    for (int i = t; i < INTER*EMB; i += 256) {
        int c = i >> 6, k = i & 63;
        W1t[k*W1T_PITCH + c] = W1[i];
    }
    for (int i = t; i < INTER; i += 256) { ss3[i] = g_s3[i]; st3[i] = g_t3[i]; sw2[i] = W2[i]; }
    float bb = b2[0];
    int tx = t & 7, ty = t >> 3;
    __syncthreads();
    for (int tile = blockIdx.x; tile < NT/32; tile += gridDim.x) {
        int row0 = tile*32;
        for (int i = t; i < 32*64; i += 256) {
            int r = i >> 6, k = i & 63;
            zrt[k*ZRT_PITCH + r] = g_zr[row0*64 + i];
        }
        if (t < 32) outp[t] = 0.f;
        __syncthreads();
        float acc[4][16];
        #pragma unroll
        for (int r = 0; r < 4; r++)
            #pragma unroll
            for (int c = 0; c < 16; c++) acc[r][c] = 0.f;
        #pragma unroll 4
        for (int k = 0; k < 64; k++) {
            float4 a = *(const float4*)&zrt[k*ZRT_PITCH + tx*4];
            float ar[4] = {a.x, a.y, a.z, a.w};
            #pragma unroll
            for (int q = 0; q < 4; q++) {
                float4 b = *(const float4*)&W1t[k*W1T_PITCH + ty*16 + q*4];
                float br[4] = {b.x, b.y, b.z, b.w};
                #pragma unroll
                for (int r = 0; r < 4; r++) {
                    acc[r][q*4+0] += ar[r]*br[0];
                    acc[r][q*4+1] += ar[r]*br[1];
                    acc[r][q*4+2] += ar[r]*br[2];
                    acc[r][q*4+3] += ar[r]*br[3];
                }
            }
        }
        float part[4] = {0,0,0,0};
        #pragma unroll
        for (int cc = 0; cc < 16; cc++) {
            int c = ty*16 + cc;
            float sc = ss3[c], sh = st3[c], w = sw2[c];
            #pragma unroll
            for (int r = 0; r < 4; r++) {
                float y = acc[r][cc]*sc + sh;
                y = fmaxf(y, 0.f);
                part[r] += y*w;
            }
        }
        #pragma unroll
        for (int r = 0; r < 4; r++) atomicAdd(&outp[tx*4 + r], part[r]);
        __syncthreads();
        if (t < 32) out[row0 + t] = outp[t] + bb;
        __syncthreads();
    }
}

// ---------------- launch ----------------
extern "C" void kernel_launch(void* const* d_in, const int* in_sizes, int n_in,
                              void* d_out, int out_size) {
    const float* data     = (const float*)d_in[0];
    /* d_in[1] org_edge_index: unused by forward */
    const float* W_emb    = (const float*)d_in[2];
    const float* W_lin    = (const float*)d_in[3];
    const float* att_i    = (const float*)d_in[4];
    const float* att_j    = (const float*)d_in[5];
    const float* att_em_i = (const float*)d_in[6];
    const float* att_em_j = (const float*)d_in[7];
    const float* b_gnn    = (const float*)d_in[8];
    const float* gbn1     = (const float*)d_in[9];
    const float* bbn1     = (const float*)d_in[10];
    const float* gbn2     = (const float*)d_in[11];
    const float* bbn2     = (const float*)d_in[12];
    const float* W1       = (const float*)d_in[13];
    const float* b1       = (const float*)d_in[14];
    const float* gbn3     = (const float*)d_in[15];
    const float* bbn3     = (const float*)d_in[16];
    const float* W2       = (const float*)d_in[17];
    const float* b2       = (const float*)d_in[18];
    float* out = (float*)d_out;

    cudaFuncSetAttribute(k_final, cudaFuncAttributeMaxDynamicSharedMemorySize, SMEM_FINAL);
    int nsm = 0;
    cudaDeviceGetAttribute(&nsm, cudaDevAttrMultiProcessorCount, 0);
    if (nsm <= 0) nsm = 148;

    k_prep<<<2, 512>>>(W_emb, att_em_i, att_em_j);
    k_topk<<<NODE, 128>>>(W_emb);
    k_xl<<<NT/64, 256>>>(data, W_lin, att_i, att_j);
    k_agg<<<NT/64, 256>>>(b_gnn);
    k_bnfin<<<1, 64>>>(gbn1, bbn1, 0);
    k_hz<<<1024, 256>>>(b_gnn, W_emb);
    k_bnfin<<<1, 64>>>(gbn2, bbn2, 1);
    k_zr<<<NT/128, 256>>>();
    k_bn3fin<<<16, 32>>>(W1, b1, gbn3, bbn3);
    k_final<<<nsm, 256, SMEM_FINAL>>>(W1, W2, b2, out);
}

// round 3
// speedup vs baseline: 1.4330x; 1.4330x over previous
#include <cuda_runtime.h>
#include <cuda_bf16.h>
#include <math.h>
#include <stdint.h>

#define BATCH 256
#define NODE  512
#define WIN   64
#define EMB   64
#define TOPK  16
#define INTER 512
#define NT    (BATCH*NODE)     /* 131072 */
#define NEG   0.2f
#define EPS   1e-5f

// ---------------- scratch (static device globals) ----------------
__device__ float g_xl[NT*EMB];
__device__ float g_agg[NT*EMB];
__device__ float g_z[NT*EMB];
__device__ __nv_bfloat162 g_zrh2[NT*EMB/2];
__device__ __nv_bfloat162 g_zrl2[NT*EMB/2];
__device__ __nv_bfloat162 g_W1h2[INTER*EMB/2];
__device__ __nv_bfloat162 g_W1l2[INTER*EMB/2];
__device__ float g_si[NT];
__device__ float g_sj[NT];
__device__ int   g_topk[NODE*TOPK];
__device__ float g_ei[NODE], g_ej[NODE], g_inv[NODE];
// [0:64]=bn1 sum  [64:128]=bn1 sq  [128:192]=bn2 sum [192:256]=bn2 sq
// [256:320]=zr colsum  [320:4416]=M2 (64x64 second moment of zr)
__device__ float g_stats[4416];
__device__ float g_sc1[EMB], g_sh1[EMB], g_sc2[EMB], g_sh2[EMB];
__device__ float4 g_abc[INTER];   // {bn3_scale, bn3_shift, W2, 0}

// ---------------- HMMA helper (baseline PTX, works on plain sm_103 target) ----------------
__device__ __forceinline__ void mma16816(float* d, const uint32_t* a, uint32_t b0, uint32_t b1) {
    asm volatile("mma.sync.aligned.m16n8k16.row.col.f32.bf16.bf16.f32 "
        "{%0,%1,%2,%3}, {%4,%5,%6,%7}, {%8,%9}, {%0,%1,%2,%3};"
        : "+f"(d[0]), "+f"(d[1]), "+f"(d[2]), "+f"(d[3])
        : "r"(a[0]), "r"(a[1]), "r"(a[2]), "r"(a[3]), "r"(b0), "r"(b1));
}

// ---------------- prep: zero stats; per-node embedding dots + inv norms ----------------
__global__ void k_prep(const float* __restrict__ W_emb,
                       const float* __restrict__ aei,
                       const float* __restrict__ aej) {
    int t = threadIdx.x;
    if (blockIdx.x == 0) {
        for (int i = t; i < 4416; i += blockDim.x) g_stats[i] = 0.f;
    } else {
        int v = t;  // 512 threads
        const float* w = W_emb + v*EMB;
        float di = 0.f, dj = 0.f, nn = 0.f;
        #pragma unroll
        for (int k = 0; k < EMB; k++) {
            float x = w[k];
            di += x*aei[k]; dj += x*aej[k]; nn += x*x;
        }
        g_ei[v] = di; g_ej[v] = dj; g_inv[v] = rsqrtf(nn);
    }
}

// ---------------- W1 -> bf16 hi/lo ----------------
__global__ void k_prepW1(const float* __restrict__ W1) {
    int i = blockIdx.x*512 + threadIdx.x;   // 16384 pairs
    if (i < INTER*EMB/2) {
        float2 w = ((const float2*)W1)[i];
        __nv_bfloat16 h0 = __float2bfloat16(w.x);
        __nv_bfloat16 h1 = __float2bfloat16(w.y);
        float f0 = __bfloat162float(h0), f1 = __bfloat162float(h1);
        g_W1h2[i] = __halves2bfloat162(h0, h1);
        g_W1l2[i] = __halves2bfloat162(__float2bfloat16(w.x - f0), __float2bfloat16(w.y - f1));
    }
}

// ---------------- cosine-similarity top-k (one block per node) ----------------
__global__ void k_topk(const float* __restrict__ W_emb) {
    __shared__ float wi[64];
    __shared__ float cosv[NODE];
    __shared__ float rv[128];
    __shared__ int   ri[128];
    int i = blockIdx.x, t = threadIdx.x;
    if (t < 64) wi[t] = W_emb[i*64 + t];
    __syncthreads();
    float inv_i = g_inv[i];
    for (int j = t; j < NODE; j += 128) {
        const float4* wj = (const float4*)&W_emb[j*64];
        float d = 0.f;
        #pragma unroll
        for (int kk = 0; kk < 16; kk++) {
            float4 b = wj[kk];
            d += wi[kk*4+0]*b.x + wi[kk*4+1]*b.y + wi[kk*4+2]*b.z + wi[kk*4+3]*b.w;
        }
        cosv[j] = d * inv_i * g_inv[j];
    }
    __syncthreads();
    for (int s = 0; s < TOPK; s++) {
        float bv = -3e38f; int bi = NODE;
        for (int j = t; j < NODE; j += 128) {
            float v = cosv[j];
            if (v > bv || (v == bv && j < bi)) { bv = v; bi = j; }
        }
        rv[t] = bv; ri[t] = bi;
        __syncthreads();
        for (int off = 64; off > 0; off >>= 1) {
            if (t < off) {
                float v2 = rv[t+off]; int i2 = ri[t+off];
                if (v2 > rv[t] || (v2 == rv[t] && i2 < ri[t])) { rv[t] = v2; ri[t] = i2; }
            }
            __syncthreads();
        }
        if (t == 0) { g_topk[i*TOPK + s] = ri[0]; cosv[ri[0]] = -3e38f; }
        __syncthreads();
    }
}

// ---------------- xl = x @ W_lin^T fused with attention scores ----------------
__global__ void k_xl(const float* __restrict__ x, const float* __restrict__ W_lin,
                     const float* __restrict__ att_i, const float* __restrict__ att_j) {
    __shared__ float As[64*68];
    __shared__ float Bs[64*68];
    __shared__ float sred[128];
    __shared__ float ai[64], aj[64];
    int t = threadIdx.x;
    int row0 = blockIdx.x * 64;
    if (t < 64) { ai[t] = att_i[t]; aj[t] = att_j[t]; }
    if (t < 128) sred[t] = 0.f;
    for (int i = t; i < 4096; i += 256) {
        int r = i >> 6, k = i & 63;
        As[k*68 + r] = x[row0*64 + i];
        Bs[k*68 + r] = W_lin[i];
    }
    __syncthreads();
    int tx = t & 15, ty = t >> 4;
    float acc[4][4];
    #pragma unroll
    for (int r = 0; r < 4; r++)
        #pragma unroll
        for (int c = 0; c < 4; c++) acc[r][c] = 0.f;
    #pragma unroll 4
    for (int k = 0; k < 64; k++) {
        float4 a = *(const float4*)&As[k*68 + ty*4];
        float4 b = *(const float4*)&Bs[k*68 + tx*4];
        float ar[4] = {a.x, a.y, a.z, a.w};
        float br[4] = {b.x, b.y, b.z, b.w};
        #pragma unroll
        for (int r = 0; r < 4; r++)
            #pragma unroll
            for (int c = 0; c < 4; c++) acc[r][c] += ar[r]*br[c];
    }
    float pi[4] = {0,0,0,0}, pj[4] = {0,0,0,0};
    #pragma unroll
    for (int r = 0; r < 4; r++) {
        float4 o = make_float4(acc[r][0], acc[r][1], acc[r][2], acc[r][3]);
        *(float4*)&g_xl[(row0 + ty*4 + r)*64 + tx*4] = o;
        #pragma unroll
        for (int c = 0; c < 4; c++) {
            pi[r] += acc[r][c]*ai[tx*4+c];
            pj[r] += acc[r][c]*aj[tx*4+c];
        }
    }
    #pragma unroll
    for (int r = 0; r < 4; r++) {
        atomicAdd(&sred[ty*4 + r], pi[r]);
        atomicAdd(&sred[64 + ty*4 + r], pj[r]);
    }
    __syncthreads();
    if (t < 64) {
        int n = row0 + t, v = n & (NODE-1);
        g_si[n] = sred[t]      + g_ei[v];
        g_sj[n] = sred[64 + t] + g_ej[v];
    }
}

// ---------------- GAT aggregation: smem-resident xl slab, LDS gather ----------------
// grid 512: block = (batch b = blk>>1, half h = blk&1); 256 threads, 8 warps.
#define AGG_XL   0                  /* 512*32 floats */
#define AGG_TK   16384              /* 8192 ints */
#define AGG_SI   24576              /* 512 */
#define AGG_SJ   25088              /* 512 */
#define AGG_W    25600              /* 8 warps * 16 float2 = 256 floats */
#define AGG_SS   25856              /* 32 */
#define AGG_SQ   25888              /* 32 */
#define SMEM_AGG ((25920)*4)
__global__ void __launch_bounds__(256, 2)
k_agg(const float* __restrict__ b_gnn) {
    extern __shared__ float smA[];
    float* sxl = smA + AGG_XL;
    int*   stk = (int*)(smA + AGG_TK);
    float* ssi = smA + AGG_SI;
    float* ssj = smA + AGG_SJ;
    float2* swp = (float2*)(smA + AGG_W);
    float* sms = smA + AGG_SS;
    float* smq = smA + AGG_SQ;
    int t = threadIdx.x, wid = t >> 5, lane = t & 31;
    int b = blockIdx.x >> 1, h = blockIdx.x & 1;
    const float4* src = (const float4*)&g_xl[b*NODE*EMB + h*32];
    for (int i = t; i < 512*8; i += 256) {
        int r = i >> 3, q = i & 7;
        ((float4*)sxl)[r*8 + q] = src[r*16 + q];
    }
    for (int i = t; i < NODE*TOPK; i += 256) stk[i] = g_topk[i];
    for (int i = t; i < NODE; i += 256) { ssi[i] = g_si[b*NODE + i]; ssj[i] = g_sj[b*NODE + i]; }
    if (t < 32) { sms[t] = 0.f; smq[t] = 0.f; }
    __syncthreads();
    int k = lane & 15;
    float bg = b_gnn[h*32 + lane];
    float s = 0.f, q = 0.f;
    float2* stage = swp + wid*16;
    for (int v = wid*64; v < wid*64 + 64; v++) {
        int nbr = stk[v*16 + k];
        float a = ssi[v] + ssj[nbr];
        a = a > 0.f ? a : NEG*a;
        float m = a;
        #pragma unroll
        for (int o = 8; o > 0; o >>= 1) m = fmaxf(m, __shfl_xor_sync(0xffffffffu, m, o, 16));
        float ex = expf(a - m);
        float den = ex;
        #pragma unroll
        for (int o = 8; o > 0; o >>= 1) den += __shfl_xor_sync(0xffffffffu, den, o, 16);
        float w = ex / den;
        if (lane < 16) stage[lane] = make_float2(w, __int_as_float(nbr));
        __syncwarp();
        float acc = 0.f;
        #pragma unroll
        for (int kk = 0; kk < 16; kk++) {
            float2 p = stage[kk];
            acc += p.x * sxl[__float_as_int(p.y)*32 + lane];
        }
        g_agg[(b*NODE + v)*EMB + h*32 + lane] = acc;
        float z = acc + bg;
        s += z; q += z*z;
        __syncwarp();
    }
    atomicAdd(&sms[lane], s);
    atomicAdd(&smq[lane], q);
    __syncthreads();
    if (t < 32) {
        atomicAdd(&g_stats[h*32 + t],      sms[t]);
        atomicAdd(&g_stats[64 + h*32 + t], smq[t]);
    }
}

// ---------------- finalize bn1/bn2 ----------------
__global__ void k_bnfin(const float* __restrict__ gamma, const float* __restrict__ beta, int which) {
    int c = threadIdx.x;
    if (c >= EMB) return;
    float s = g_stats[which*128 + c], q = g_stats[which*128 + 64 + c];
    float m = s * (1.f/NT);
    float v = q * (1.f/NT) - m*m;
    float sc = gamma[c] * rsqrtf(v + EPS);
    float sh = beta[c] - m*sc;
    if (which == 0) { g_sc1[c] = sc; g_sh1[c] = sh; }
    else            { g_sc2[c] = sc; g_sh2[c] = sh; }
}

// ---------------- h = relu(bn1(agg+b)); z = h * W_emb ; bn2 stats ----------------
__global__ void k_hz(const float* __restrict__ b_gnn, const float* __restrict__ W_emb) {
    __shared__ float sm_s[64], sm_q[64];
    int t = threadIdx.x;
    if (t < 64) { sm_s[t] = 0.f; sm_q[t] = 0.f; }
    __syncthreads();
    int gt = blockIdx.x*256 + t;
    int cp = gt & 31;
    int c0 = cp*2;
    float sc0 = g_sc1[c0], sc1v = g_sc1[c0+1];
    float sh0 = g_sh1[c0], sh1v = g_sh1[c0+1];
    float bg0 = b_gnn[c0], bg1 = b_gnn[c0+1];
    float s0=0,q0=0,s1=0,q1=0;
    const float2* a2 = (const float2*)g_agg;
    float2* z2 = (float2*)g_z;
    const int stride = 1024*256;
    for (int idx = gt; idx < NT*32; idx += stride) {
        int row = idx >> 5;
        int v = row & (NODE-1);
        float2 a = a2[idx];
        float h0 = fmaxf((a.x + bg0)*sc0 + sh0, 0.f);
        float h1 = fmaxf((a.y + bg1)*sc1v + sh1v, 0.f);
        float2 we = *(const float2*)&W_emb[v*EMB + c0];
        float z0 = h0 * we.x;
        float z1 = h1 * we.y;
        z2[idx] = make_float2(z0, z1);
        s0 += z0; q0 += z0*z0; s1 += z1; q1 += z1*z1;
    }
    atomicAdd(&sm_s[c0],   s0); atomicAdd(&sm_q[c0],   q0);
    atomicAdd(&sm_s[c0+1], s1); atomicAdd(&sm_q[c0+1], q1);
    __syncthreads();
    if (t < 64) { atomicAdd(&g_stats[128+t], sm_s[t]); atomicAdd(&g_stats[192+t], sm_q[t]); }
}

// ---------------- zr = relu(bn2(z)); emit bf16 hi/lo; SYRK + colsum (persistent) ----------------
__global__ void __launch_bounds__(256, 1)
k_zr() {
    __shared__ float zs[128*68];
    __shared__ float ssc[64], ssh[64];
    __shared__ float red[256];
    int t = threadIdx.x;
    if (t < 64) { ssc[t] = g_sc2[t]; ssh[t] = g_sh2[t]; }
    int tx = t & 15, ty = t >> 4;
    int a0 = ty*4, b0 = tx*4;
    float acc[4][4];
    #pragma unroll
    for (int i = 0; i < 4; i++)
        #pragma unroll
        for (int j = 0; j < 4; j++) acc[i][j] = 0.f;
    float csum = 0.f;
    int cc = t & 63, rr0 = t >> 6;
    for (int tile = blockIdx.x; tile < NT/128; tile += gridDim.x) {
        int row0 = tile << 7;
        __syncthreads();
        for (int i = t; i < 128*32; i += 256) {
            int r = i >> 5, c0 = (i & 31)*2;
            float2 v = ((const float2*)g_z)[row0*32 + i];
            float z0 = fmaxf(fmaf(v.x, ssc[c0],   ssh[c0]),   0.f);
            float z1 = fmaxf(fmaf(v.y, ssc[c0+1], ssh[c0+1]), 0.f);
            zs[r*68 + c0] = z0; zs[r*68 + c0 + 1] = z1;
            __nv_bfloat16 h0 = __float2bfloat16(z0);
            __nv_bfloat16 h1 = __float2bfloat16(z1);
            float f0 = __bfloat162float(h0), f1 = __bfloat162float(h1);
            g_zrh2[row0*32 + i] = __halves2bfloat162(h0, h1);
            g_zrl2[row0*32 + i] = __halves2bfloat162(__float2bfloat16(z0 - f0),
                                                     __float2bfloat16(z1 - f1));
        }
        __syncthreads();
        for (int r = rr0; r < 128; r += 4) csum += zs[r*68 + cc];
        #pragma unroll 4
        for (int r = 0; r < 128; r++) {
            float4 va = *(const float4*)&zs[r*68 + a0];
            float4 vb = *(const float4*)&zs[r*68 + b0];
            float av[4] = {va.x, va.y, va.z, va.w};
            float bv[4] = {vb.x, vb.y, vb.z, vb.w};
            #pragma unroll
            for (int i = 0; i < 4; i++)
                #pragma unroll
                for (int j = 0; j < 4; j++) acc[i][j] += av[i]*bv[j];
        }
    }
    __syncthreads();
    red[t] = csum;
    __syncthreads();
    if (t < 64) atomicAdd(&g_stats[256 + t], red[t] + red[64+t] + red[128+t] + red[192+t]);
    #pragma unroll
    for (int i = 0; i < 4; i++)
        #pragma unroll
        for (int j = 0; j < 4; j++)
            atomicAdd(&g_stats[320 + (a0+i)*64 + b0 + j], acc[i][j]);
}

// ---------------- analytic BN3: mean/var of y=zr@W1^T+b1 from (zbar, Cov); pack {sc,sh,w2} ----------------
__global__ void k_bn3fin(const float* __restrict__ W1, const float* __restrict__ b1,
                         const float* __restrict__ g3, const float* __restrict__ b3,
                         const float* __restrict__ W2) {
    __shared__ float Cov[EMB*EMB];
    __shared__ float zb[EMB];
    int t = threadIdx.x;
    for (int i = t; i < EMB; i += 32) zb[i] = g_stats[256+i] * (1.f/NT);
    __syncthreads();
    for (int i = t; i < EMB*EMB; i += 32)
        Cov[i] = g_stats[320+i] * (1.f/NT) - zb[i >> 6]*zb[i & 63];
    __syncthreads();
    int c = blockIdx.x*32 + t;
    const float* wc = W1 + c*EMB;
    float wr[EMB];
    #pragma unroll
    for (int k = 0; k < EMB; k++) wr[k] = wc[k];
    float m = b1[c];
    #pragma unroll
    for (int k = 0; k < EMB; k++) m += zb[k]*wr[k];
    float var = 0.f;
    for (int a = 0; a < EMB; a++) {
        float ta = 0.f;
        #pragma unroll 8
        for (int b = 0; b < EMB; b++) ta += Cov[a*EMB + b]*wr[b];
        var += ta * wr[a];
    }
    float sc = g3[c] * rsqrtf(var + EPS);
    g_abc[c] = make_float4(sc, b3[c] - m*sc, W2[c], 0.f);
}

// ---------------- final: HMMA bf16-split GEMM + fused bn3/relu/W2 epilogue ----------------
// smem layout (uint32 words): Bh[512*36], Bl[512*36], Ah[128*36], Al[128*36], abc float4[512]
#define FM_BH   0
#define FM_BL   18432
#define FM_AH   36864
#define FM_AL   41472
#define FM_ABC  46080
#define SMEM_FM ((46080 + 2048)*4)   /* 192512 B */

__global__ void __launch_bounds__(256, 1)
k_final_mma(const float* __restrict__ b2, float* __restrict__ out) {
    extern __shared__ uint32_t sm4[];
    uint32_t* Bh = sm4 + FM_BH;
    uint32_t* Bl = sm4 + FM_BL;
    uint32_t* Ah = sm4 + FM_AH;
    uint32_t* Al = sm4 + FM_AL;
    float4*   abc = (float4*)(sm4 + FM_ABC);
    int t = threadIdx.x, lane = t & 31, wid = t >> 5;
    const uint32_t* wh = (const uint32_t*)g_W1h2;
    const uint32_t* wl = (const uint32_t*)g_W1l2;
    for (int i = t; i < 512*32; i += 256) {
        int n = i >> 5, k2 = i & 31;
        Bh[n*36 + k2] = wh[i];
        Bl[n*36 + k2] = wl[i];
    }
    for (int i = t; i < 512; i += 256) abc[i] = g_abc[i];
    float bb = b2[0];
    int g = lane >> 2, tid = lane & 3;
    int r0 = wid*16 + g;

    for (int tile = blockIdx.x; tile < NT/128; tile += gridDim.x) {
        int row0 = tile << 7;
        __syncthreads();   // previous iteration's A readers done
        const uint32_t* zh = (const uint32_t*)g_zrh2 + row0*32;
        const uint32_t* zl = (const uint32_t*)g_zrl2 + row0*32;
        for (int i = t; i < 128*32; i += 256) {
            int r = i >> 5, k2 = i & 31;
            Ah[r*36 + k2] = zh[i];
            Al[r*36 + k2] = zl[i];
        }
        __syncthreads();
        // A fragments for this warp's 16 rows (K=64 -> 4 k-steps), hi and lo
        uint32_t ah[4][4], al[4][4];
        #pragma unroll
        for (int ks = 0; ks < 4; ks++) {
            ah[ks][0] = Ah[r0*36       + ks*8 + tid];
            ah[ks][1] = Ah[(r0+8)*36   + ks*8 + tid];
            ah[ks][2] = Ah[r0*36       + ks*8 + tid + 4];
            ah[ks][3] = Ah[(r0+8)*36   + ks*8 + tid + 4];
            al[ks][0] = Al[r0*36       + ks*8 + tid];
            al[ks][1] = Al[(r0+8)*36   + ks*8 + tid];
            al[ks][2] = Al[r0*36       + ks*8 + tid + 4];
            al[ks][3] = Al[(r0+8)*36   + ks*8 + tid + 4];
        }
        float part0 = 0.f, part1 = 0.f;
        #pragma unroll 2
        for (int nt = 0; nt < 64; nt++) {
            float hh[4] = {0,0,0,0}, hl[4] = {0,0,0,0}, lh[4] = {0,0,0,0};
            int nb = (nt*8 + g)*36;
            #pragma unroll
            for (int ks = 0; ks < 4; ks++) {
                uint32_t bh0 = Bh[nb + ks*8 + tid], bh1 = Bh[nb + ks*8 + tid + 4];
                uint32_t bl0 = Bl[nb + ks*8 + tid], bl1 = Bl[nb + ks*8 + tid + 4];
                mma16816(hh, ah[ks], bh0, bh1);
                mma16816(hl, ah[ks], bl0, bl1);
                mma16816(lh, al[ks], bh0, bh1);
            }
            float4 p0 = abc[nt*8 + tid*2];
            float4 p1 = abc[nt*8 + tid*2 + 1];
            float y;
            y = fmaxf(fmaf(hh[0]+hl[0]+lh[0], p0.x, p0.y), 0.f); part0 = fmaf(y, p0.z, part0);
            y = fmaxf(fmaf(hh[1]+hl[1]+lh[1], p1.x, p1.y), 0.f); part0 = fmaf(y, p1.z, part0);
            y = fmaxf(fmaf(hh[2]+hl[2]+lh[2], p0.x, p0.y), 0.f); part1 = fmaf(y, p0.z, part1);
            y = fmaxf(fmaf(hh[3]+hl[3]+lh[3], p1.x, p1.y), 0.f); part1 = fmaf(y, p1.z, part1);
        }
        // reduce across the 4 threads of each row group (lanes g*4..g*4+3)
        part0 += __shfl_xor_sync(0xffffffffu, part0, 1);
        part0 += __shfl_xor_sync(0xffffffffu, part0, 2);
        part1 += __shfl_xor_sync(0xffffffffu, part1, 1);
        part1 += __shfl_xor_sync(0xffffffffu, part1, 2);
        if (tid == 0) {
            out[row0 + r0]     = part0 + bb;
            out[row0 + r0 + 8] = part1 + bb;
        }
    }
}

// ---------------- launch ----------------
extern "C" void kernel_launch(void* const* d_in, const int* in_sizes, int n_in,
                              void* d_out, int out_size) {
    const float* data     = (const float*)d_in[0];
    const float* W_emb    = (const float*)d_in[2];
    const float* W_lin    = (const float*)d_in[3];
    const float* att_i    = (const float*)d_in[4];
    const float* att_j    = (const float*)d_in[5];
    const float* att_em_i = (const float*)d_in[6];
    const float* att_em_j = (const float*)d_in[7];
    const float* b_gnn    = (const float*)d_in[8];
    const float* gbn1     = (const float*)d_in[9];
    const float* bbn1     = (const float*)d_in[10];
    const float* gbn2     = (const float*)d_in[11];
    const float* bbn2     = (const float*)d_in[12];
    const float* W1       = (const float*)d_in[13];
    const float* b1       = (const float*)d_in[14];
    const float* gbn3     = (const float*)d_in[15];
    const float* bbn3     = (const float*)d_in[16];
    const float* W2       = (const float*)d_in[17];
    const float* b2       = (const float*)d_in[18];
    float* out = (float*)d_out;

    cudaFuncSetAttribute(k_agg,       cudaFuncAttributeMaxDynamicSharedMemorySize, SMEM_AGG);
    cudaFuncSetAttribute(k_final_mma, cudaFuncAttributeMaxDynamicSharedMemorySize, SMEM_FM);
    int nsm = 0;
    cudaDeviceGetAttribute(&nsm, cudaDevAttrMultiProcessorCount, 0);
    if (nsm <= 0) nsm = 148;

    k_prep<<<2, 512>>>(W_emb, att_em_i, att_em_j);
    k_prepW1<<<32, 512>>>(W1);
    k_topk<<<NODE, 128>>>(W_emb);
    k_xl<<<NT/64, 256>>>(data, W_lin, att_i, att_j);
    k_agg<<<512, 256, SMEM_AGG>>>(b_gnn);
    k_bnfin<<<1, 64>>>(gbn1, bbn1, 0);
    k_hz<<<1024, 256>>>(b_gnn, W_emb);
    k_bnfin<<<1, 64>>>(gbn2, bbn2, 1);
    k_zr<<<nsm, 256>>>();
    k_bn3fin<<<16, 32>>>(W1, b1, gbn3, bbn3, W2);
    k_final_mma<<<nsm, 256, SMEM_FM>>>(b2, out);
}

// round 4
// speedup vs baseline: 1.6063x; 1.1209x over previous
#include <cuda_runtime.h>
#include <cuda_bf16.h>
#include <math.h>
#include <stdint.h>

#define BATCH 256
#define NODE  512
#define WIN   64
#define EMB   64
#define TOPK  16
#define INTER 512
#define NT    (BATCH*NODE)     /* 131072 */
#define NEG   0.2f
#define EPS   1e-5f

// ---------------- scratch (static device globals) ----------------
__device__ float g_xl[NT*EMB];
__device__ float g_agg[NT*EMB];
__device__ __nv_bfloat162 g_zrh2[NT*EMB/2];
__device__ __nv_bfloat162 g_zrl2[NT*EMB/2];
__device__ __nv_bfloat162 g_W1h2[INTER*EMB/2];
__device__ __nv_bfloat162 g_W1l2[INTER*EMB/2];
__device__ float g_si[NT];
__device__ float g_sj[NT];
__device__ int   g_topk[NODE*TOPK];
__device__ float g_ei[NODE], g_ej[NODE], g_inv[NODE];
// [0:64]=bn1 sum  [64:128]=bn1 sq  [128:192]=bn2 sum [192:256]=bn2 sq
// [256:320]=zr colsum  [320:4416]=M2 (64x64 second moment of zr)
__device__ float g_stats[4416];
__device__ float g_sc1[EMB], g_sh1[EMB], g_sc2[EMB], g_sh2[EMB];
__device__ float4 g_abc[INTER];   // {bn3_scale, bn3_shift, W2, 0}

// ---------------- HMMA helper ----------------
__device__ __forceinline__ void mma16816(float* d, const uint32_t* a, uint32_t b0, uint32_t b1) {
    asm volatile("mma.sync.aligned.m16n8k16.row.col.f32.bf16.bf16.f32 "
        "{%0,%1,%2,%3}, {%4,%5,%6,%7}, {%8,%9}, {%0,%1,%2,%3};"
        : "+f"(d[0]), "+f"(d[1]), "+f"(d[2]), "+f"(d[3])
        : "r"(a[0]), "r"(a[1]), "r"(a[2]), "r"(a[3]), "r"(b0), "r"(b1));
}
// fragment-order permutation of a 32-word (64 bf16) k-row:
// j = tid*8 + ks*2 + h   (tid=k2&3, h=(k2>>2)&1, ks=k2>>3)
__device__ __forceinline__ int fragperm(int k2) {
    return (k2 & 3)*8 + (k2 >> 3)*2 + ((k2 >> 2) & 1);
}
__device__ __forceinline__ uint32_t packsplit(float x, float y, uint32_t* lo) {
    __nv_bfloat16 h0 = __float2bfloat16(x);
    __nv_bfloat16 h1 = __float2bfloat16(y);
    __nv_bfloat162 l2 = __halves2bfloat162(__float2bfloat16(x - __bfloat162float(h0)),
                                           __float2bfloat16(y - __bfloat162float(h1)));
    *lo = *(uint32_t*)&l2;
    __nv_bfloat162 h2 = __halves2bfloat162(h0, h1);
    return *(uint32_t*)&h2;
}

// ---------------- prep: zero stats; per-node embedding dots + inv norms ----------------
__global__ void k_prep(const float* __restrict__ W_emb,
                       const float* __restrict__ aei,
                       const float* __restrict__ aej) {
    int t = threadIdx.x;
    if (blockIdx.x == 0) {
        for (int i = t; i < 4416; i += blockDim.x) g_stats[i] = 0.f;
    } else {
        int v = t;
        const float* w = W_emb + v*EMB;
        float di = 0.f, dj = 0.f, nn = 0.f;
        #pragma unroll
        for (int k = 0; k < EMB; k++) {
            float x = w[k];
            di += x*aei[k]; dj += x*aej[k]; nn += x*x;
        }
        g_ei[v] = di; g_ej[v] = dj; g_inv[v] = rsqrtf(nn);
    }
}

// ---------------- W1 -> bf16 hi/lo ----------------
__global__ void k_prepW1(const float* __restrict__ W1) {
    int i = blockIdx.x*512 + threadIdx.x;
    if (i < INTER*EMB/2) {
        float2 w = ((const float2*)W1)[i];
        uint32_t lo, hi = packsplit(w.x, w.y, &lo);
        ((uint32_t*)g_W1h2)[i] = hi;
        ((uint32_t*)g_W1l2)[i] = lo;
    }
}

// ---------------- cosine-similarity top-k (one block per node) ----------------
__global__ void k_topk(const float* __restrict__ W_emb) {
    __shared__ float wi[64];
    __shared__ float cosv[NODE];
    __shared__ float rv[128];
    __shared__ int   ri[128];
    int i = blockIdx.x, t = threadIdx.x;
    if (t < 64) wi[t] = W_emb[i*64 + t];
    __syncthreads();
    float inv_i = g_inv[i];
    for (int j = t; j < NODE; j += 128) {
        const float4* wj = (const float4*)&W_emb[j*64];
        float d = 0.f;
        #pragma unroll
        for (int kk = 0; kk < 16; kk++) {
            float4 b = wj[kk];
            d += wi[kk*4+0]*b.x + wi[kk*4+1]*b.y + wi[kk*4+2]*b.z + wi[kk*4+3]*b.w;
        }
        cosv[j] = d * inv_i * g_inv[j];
    }
    __syncthreads();
    for (int s = 0; s < TOPK; s++) {
        float bv = -3e38f; int bi = NODE;
        for (int j = t; j < NODE; j += 128) {
            float v = cosv[j];
            if (v > bv || (v == bv && j < bi)) { bv = v; bi = j; }
        }
        rv[t] = bv; ri[t] = bi;
        __syncthreads();
        for (int off = 64; off > 0; off >>= 1) {
            if (t < off) {
                float v2 = rv[t+off]; int i2 = ri[t+off];
                if (v2 > rv[t] || (v2 == rv[t] && i2 < ri[t])) { rv[t] = v2; ri[t] = i2; }
            }
            __syncthreads();
        }
        if (t == 0) { g_topk[i*TOPK + s] = ri[0]; cosv[ri[0]] = -3e38f; }
        __syncthreads();
    }
}

// ---------------- xl = x @ W_lin^T via HMMA split + fused attention scores ----------------
// smem word offsets
#define XL_BH 0         /* 64*36  */
#define XL_BL 2304
#define XL_AH 4608      /* 128*36 */
#define XL_AL 9216
#define XL_AI 13824
#define XL_AJ 13888
#define SMEM_XL (13952*4)
__global__ void __launch_bounds__(256, 2)
k_xl_mma(const float* __restrict__ x, const float* __restrict__ W_lin,
         const float* __restrict__ att_i, const float* __restrict__ att_j) {
    extern __shared__ uint32_t smx[];
    uint32_t* Bh = smx + XL_BH;
    uint32_t* Bl = smx + XL_BL;
    uint32_t* Ah = smx + XL_AH;
    uint32_t* Al = smx + XL_AL;
    float* ai = (float*)(smx + XL_AI);
    float* aj = (float*)(smx + XL_AJ);
    int t = threadIdx.x, lane = t & 31, wid = t >> 5;
    int g = lane >> 2, tid = lane & 3;
    // stage W_lin hi/lo fragment-ordered
    for (int i = t; i < 64*32; i += 256) {
        int e = i >> 5, k2 = i & 31;
        float2 w = ((const float2*)W_lin)[i];
        uint32_t lo, hi = packsplit(w.x, w.y, &lo);
        int j = fragperm(k2);
        Bh[e*36 + j] = hi; Bl[e*36 + j] = lo;
    }
    if (t < 64) { ai[t] = att_i[t]; aj[t] = att_j[t]; }
    int r0 = wid*16 + g;
    for (int tile = blockIdx.x; tile < NT/128; tile += gridDim.x) {
        int row0 = tile << 7;
        __syncthreads();
        for (int i = t; i < 128*32; i += 256) {
            int r = i >> 5, k2 = i & 31;
            float2 v = ((const float2*)x)[row0*32 + i];
            uint32_t lo, hi = packsplit(v.x, v.y, &lo);
            int j = fragperm(k2);
            Ah[r*36 + j] = hi; Al[r*36 + j] = lo;
        }
        __syncthreads();
        uint4 qh0 = *(const uint4*)&Ah[r0*36 + tid*8];
        uint4 qh1 = *(const uint4*)&Ah[r0*36 + tid*8 + 4];
        uint4 qh2 = *(const uint4*)&Ah[(r0+8)*36 + tid*8];
        uint4 qh3 = *(const uint4*)&Ah[(r0+8)*36 + tid*8 + 4];
        uint4 ql0 = *(const uint4*)&Al[r0*36 + tid*8];
        uint4 ql1 = *(const uint4*)&Al[r0*36 + tid*8 + 4];
        uint4 ql2 = *(const uint4*)&Al[(r0+8)*36 + tid*8];
        uint4 ql3 = *(const uint4*)&Al[(r0+8)*36 + tid*8 + 4];
        uint32_t ah[4][4] = {
            {qh0.x, qh2.x, qh0.y, qh2.y}, {qh0.z, qh2.z, qh0.w, qh2.w},
            {qh1.x, qh3.x, qh1.y, qh3.y}, {qh1.z, qh3.z, qh1.w, qh3.w}};
        uint32_t al[4][4] = {
            {ql0.x, ql2.x, ql0.y, ql2.y}, {ql0.z, ql2.z, ql0.w, ql2.w},
            {ql1.x, ql3.x, ql1.y, ql3.y}, {ql1.z, ql3.z, ql1.w, ql3.w}};
        float pi0=0, pi1=0, pj0=0, pj1=0;
        #pragma unroll
        for (int nt = 0; nt < 8; nt++) {
            int nb = (nt*8 + g)*36 + tid*8;
            uint4 bh0 = *(const uint4*)&Bh[nb], bh1 = *(const uint4*)&Bh[nb+4];
            uint4 bl0 = *(const uint4*)&Bl[nb], bl1 = *(const uint4*)&Bl[nb+4];
            float hh[4]={0,0,0,0}, hl[4]={0,0,0,0}, lh[4]={0,0,0,0};
            mma16816(hh, ah[0], bh0.x, bh0.y); mma16816(hh, ah[1], bh0.z, bh0.w);
            mma16816(hh, ah[2], bh1.x, bh1.y); mma16816(hh, ah[3], bh1.z, bh1.w);
            mma16816(hl, ah[0], bl0.x, bl0.y); mma16816(hl, ah[1], bl0.z, bl0.w);
            mma16816(hl, ah[2], bl1.x, bl1.y); mma16816(hl, ah[3], bl1.z, bl1.w);
            mma16816(lh, al[0], bh0.x, bh0.y); mma16816(lh, al[1], bh0.z, bh0.w);
            mma16816(lh, al[2], bh1.x, bh1.y); mma16816(lh, al[3], bh1.z, bh1.w);
            float v0 = hh[0]+hl[0]+lh[0], v1 = hh[1]+hl[1]+lh[1];
            float v2 = hh[2]+hl[2]+lh[2], v3 = hh[3]+hl[3]+lh[3];
            int col = nt*8 + tid*2;
            *(float2*)&g_xl[(row0+r0)*64 + col]   = make_float2(v0, v1);
            *(float2*)&g_xl[(row0+r0+8)*64 + col] = make_float2(v2, v3);
            float a0 = ai[col], a1 = ai[col+1], j0 = aj[col], j1 = aj[col+1];
            pi0 += v0*a0 + v1*a1;  pj0 += v0*j0 + v1*j1;
            pi1 += v2*a0 + v3*a1;  pj1 += v2*j0 + v3*j1;
        }
        pi0 += __shfl_xor_sync(0xffffffffu, pi0, 1); pi0 += __shfl_xor_sync(0xffffffffu, pi0, 2);
        pj0 += __shfl_xor_sync(0xffffffffu, pj0, 1); pj0 += __shfl_xor_sync(0xffffffffu, pj0, 2);
        pi1 += __shfl_xor_sync(0xffffffffu, pi1, 1); pi1 += __shfl_xor_sync(0xffffffffu, pi1, 2);
        pj1 += __shfl_xor_sync(0xffffffffu, pj1, 1); pj1 += __shfl_xor_sync(0xffffffffu, pj1, 2);
        if (tid == 0) {
            int n0 = row0 + r0, v = n0 & (NODE-1);
            g_si[n0] = pi0 + g_ei[v]; g_sj[n0] = pj0 + g_ej[v];
            n0 += 8; v = n0 & (NODE-1);
            g_si[n0] = pi1 + g_ei[v]; g_sj[n0] = pj1 + g_ej[v];
        }
    }
}

// ---------------- GAT aggregation: smem-resident xl slab, LDS gather ----------------
#define AGG_XL   0
#define AGG_TK   16384
#define AGG_SI   24576
#define AGG_SJ   25088
#define AGG_W    25600
#define AGG_SS   25856
#define AGG_SQ   25888
#define SMEM_AGG ((25920)*4)
__global__ void __launch_bounds__(256, 2)
k_agg(const float* __restrict__ b_gnn) {
    extern __shared__ float smA[];
    float* sxl = smA + AGG_XL;
    int*   stk = (int*)(smA + AGG_TK);
    float* ssi = smA + AGG_SI;
    float* ssj = smA + AGG_SJ;
    float2* swp = (float2*)(smA + AGG_W);
    float* sms = smA + AGG_SS;
    float* smq = smA + AGG_SQ;
    int t = threadIdx.x, wid = t >> 5, lane = t & 31;
    int b = blockIdx.x >> 1, h = blockIdx.x & 1;
    const float4* src = (const float4*)&g_xl[b*NODE*EMB + h*32];
    for (int i = t; i < 512*8; i += 256) {
        int r = i >> 3, q = i & 7;
        ((float4*)sxl)[r*8 + q] = src[r*16 + q];
    }
    for (int i = t; i < NODE*TOPK; i += 256) stk[i] = g_topk[i];
    for (int i = t; i < NODE; i += 256) { ssi[i] = g_si[b*NODE + i]; ssj[i] = g_sj[b*NODE + i]; }
    if (t < 32) { sms[t] = 0.f; smq[t] = 0.f; }
    __syncthreads();
    int k = lane & 15;
    float bg = b_gnn[h*32 + lane];
    float s = 0.f, q = 0.f;
    float2* stage = swp + wid*16;
    for (int v = wid*64; v < wid*64 + 64; v++) {
        int nbr = stk[v*16 + k];
        float a = ssi[v] + ssj[nbr];
        a = a > 0.f ? a : NEG*a;
        float m = a;
        #pragma unroll
        for (int o = 8; o > 0; o >>= 1) m = fmaxf(m, __shfl_xor_sync(0xffffffffu, m, o, 16));
        float ex = expf(a - m);
        float den = ex;
        #pragma unroll
        for (int o = 8; o > 0; o >>= 1) den += __shfl_xor_sync(0xffffffffu, den, o, 16);
        float w = ex / den;
        if (lane < 16) stage[lane] = make_float2(w, __int_as_float(nbr));
        __syncwarp();
        float acc = 0.f;
        #pragma unroll
        for (int kk = 0; kk < 16; kk++) {
            float2 p = stage[kk];
            acc += p.x * sxl[__float_as_int(p.y)*32 + lane];
        }
        g_agg[(b*NODE + v)*EMB + h*32 + lane] = acc;
        float z = acc + bg;
        s += z; q += z*z;
        __syncwarp();
    }
    atomicAdd(&sms[lane], s);
    atomicAdd(&smq[lane], q);
    __syncthreads();
    if (t < 32) {
        atomicAdd(&g_stats[h*32 + t],      sms[t]);
        atomicAdd(&g_stats[64 + h*32 + t], smq[t]);
    }
}

// ---------------- finalize bn1/bn2 ----------------
__global__ void k_bnfin(const float* __restrict__ gamma, const float* __restrict__ beta, int which) {
    int c = threadIdx.x;
    if (c >= EMB) return;
    float s = g_stats[which*128 + c], q = g_stats[which*128 + 64 + c];
    float m = s * (1.f/NT);
    float v = q * (1.f/NT) - m*m;
    float sc = gamma[c] * rsqrtf(v + EPS);
    float sh = beta[c] - m*sc;
    if (which == 0) { g_sc1[c] = sc; g_sh1[c] = sh; }
    else            { g_sc2[c] = sc; g_sh2[c] = sh; }
}

// ---------------- bn2 stats from agg (no z materialization) ----------------
__global__ void k_hz2(const float* __restrict__ b_gnn, const float* __restrict__ W_emb) {
    __shared__ float sm_s[64], sm_q[64];
    int t = threadIdx.x;
    if (t < 64) { sm_s[t] = 0.f; sm_q[t] = 0.f; }
    __syncthreads();
    int gt = blockIdx.x*256 + t;
    int c0 = (gt & 31)*2;
    float A0 = g_sc1[c0], A1 = g_sc1[c0+1];
    float B0 = fmaf(b_gnn[c0],   A0, g_sh1[c0]);
    float B1 = fmaf(b_gnn[c0+1], A1, g_sh1[c0+1]);
    float s0=0,q0=0,s1=0,q1=0;
    const float2* a2 = (const float2*)g_agg;
    const int stride = 1024*256;
    for (int idx = gt; idx < NT*32; idx += stride) {
        int row = idx >> 5;
        int v = row & (NODE-1);
        float2 a = a2[idx];
        float h0 = fmaxf(fmaf(a.x, A0, B0), 0.f);
        float h1 = fmaxf(fmaf(a.y, A1, B1), 0.f);
        float2 we = *(const float2*)&W_emb[v*EMB + c0];
        float z0 = h0 * we.x;
        float z1 = h1 * we.y;
        s0 += z0; q0 += z0*z0; s1 += z1; q1 += z1*z1;
    }
    atomicAdd(&sm_s[c0],   s0); atomicAdd(&sm_q[c0],   q0);
    atomicAdd(&sm_s[c0+1], s1); atomicAdd(&sm_q[c0+1], q1);
    __syncthreads();
    if (t < 64) { atomicAdd(&g_stats[128+t], sm_s[t]); atomicAdd(&g_stats[192+t], sm_q[t]); }
}

// ---------------- zr from agg; emit bf16 hi/lo (fragment-ordered source layout is natural);
//                  SYRK + colsum (persistent) ----------------
__global__ void __launch_bounds__(256, 1)
k_zr(const float* __restrict__ b_gnn, const float* __restrict__ W_emb) {
    __shared__ float zs[128*68];
    __shared__ float cA[64], cB[64], c2s[64], c2h[64];
    __shared__ float red[256];
    int t = threadIdx.x;
    if (t < 64) {
        float sc = g_sc1[t];
        cA[t] = sc;
        cB[t] = fmaf(b_gnn[t], sc, g_sh1[t]);
        c2s[t] = g_sc2[t]; c2h[t] = g_sh2[t];
    }
    int tx = t & 15, ty = t >> 4;
    int a0 = ty*4, b0 = tx*4;
    float acc[4][4];
    #pragma unroll
    for (int i = 0; i < 4; i++)
        #pragma unroll
        for (int j = 0; j < 4; j++) acc[i][j] = 0.f;
    float csum = 0.f;
    int cc = t & 63, rr0 = t >> 6;
    for (int tile = blockIdx.x; tile < NT/128; tile += gridDim.x) {
        int row0 = tile << 7;
        __syncthreads();
        for (int i = t; i < 128*32; i += 256) {
            int r = i >> 5, c0 = (i & 31)*2;
            int v = (row0 + r) & (NODE-1);
            float2 a = ((const float2*)g_agg)[row0*32 + i];
            float2 we = *(const float2*)&W_emb[v*EMB + c0];
            float h0 = fmaxf(fmaf(a.x, cA[c0],   cB[c0]),   0.f);
            float h1 = fmaxf(fmaf(a.y, cA[c0+1], cB[c0+1]), 0.f);
            float z0 = fmaxf(fmaf(h0*we.x, c2s[c0],   c2h[c0]),   0.f);
            float z1 = fmaxf(fmaf(h1*we.y, c2s[c0+1], c2h[c0+1]), 0.f);
            zs[r*68 + c0] = z0; zs[r*68 + c0 + 1] = z1;
            uint32_t lo, hi = packsplit(z0, z1, &lo);
            ((uint32_t*)g_zrh2)[row0*32 + i] = hi;
            ((uint32_t*)g_zrl2)[row0*32 + i] = lo;
        }
        __syncthreads();
        for (int r = rr0; r < 128; r += 4) csum += zs[r*68 + cc];
        #pragma unroll 4
        for (int r = 0; r < 128; r++) {
            float4 va = *(const float4*)&zs[r*68 + a0];
            float4 vb = *(const float4*)&zs[r*68 + b0];
            float av[4] = {va.x, va.y, va.z, va.w};
            float bv[4] = {vb.x, vb.y, vb.z, vb.w};
            #pragma unroll
            for (int i = 0; i < 4; i++)
                #pragma unroll
                for (int j = 0; j < 4; j++) acc[i][j] += av[i]*bv[j];
        }
    }
    __syncthreads();
    red[t] = csum;
    __syncthreads();
    if (t < 64) atomicAdd(&g_stats[256 + t], red[t] + red[64+t] + red[128+t] + red[192+t]);
    #pragma unroll
    for (int i = 0; i < 4; i++)
        #pragma unroll
        for (int j = 0; j < 4; j++)
            atomicAdd(&g_stats[320 + (a0+i)*64 + b0 + j], acc[i][j]);
}

// ---------------- analytic BN3: pack {sc,sh,w2} ----------------
__global__ void k_bn3fin(const float* __restrict__ W1, const float* __restrict__ b1,
                         const float* __restrict__ g3, const float* __restrict__ b3,
                         const float* __restrict__ W2) {
    __shared__ float Cov[EMB*EMB];
    __shared__ float zb[EMB];
    int t = threadIdx.x;
    for (int i = t; i < EMB; i += 32) zb[i] = g_stats[256+i] * (1.f/NT);
    __syncthreads();
    for (int i = t; i < EMB*EMB; i += 32)
        Cov[i] = g_stats[320+i] * (1.f/NT) - zb[i >> 6]*zb[i & 63];
    __syncthreads();
    int c = blockIdx.x*32 + t;
    const float* wc = W1 + c*EMB;
    float wr[EMB];
    #pragma unroll
    for (int k = 0; k < EMB; k++) wr[k] = wc[k];
    float m = b1[c];
    #pragma unroll
    for (int k = 0; k < EMB; k++) m += zb[k]*wr[k];
    float var = 0.f;
    for (int a = 0; a < EMB; a++) {
        float ta = 0.f;
        #pragma unroll 8
        for (int b = 0; b < EMB; b++) ta += Cov[a*EMB + b]*wr[b];
        var += ta * wr[a];
    }
    float sc = g3[c] * rsqrtf(var + EPS);
    g_abc[c] = make_float4(sc, b3[c] - m*sc, W2[c], 0.f);
}

// ---------------- final: HMMA bf16-split GEMM + fused bn3/relu/W2 epilogue ----------------
#define FM_BH   0
#define FM_BL   18432
#define FM_AH   36864
#define FM_AL   41472
#define FM_ABC  46080
#define SMEM_FM ((46080 + 2048)*4)   /* 192512 B */

__global__ void __launch_bounds__(256, 1)
k_final_mma(const float* __restrict__ b2, float* __restrict__ out) {
    extern __shared__ uint32_t sm4[];
    uint32_t* Bh = sm4 + FM_BH;
    uint32_t* Bl = sm4 + FM_BL;
    uint32_t* Ah = sm4 + FM_AH;
    uint32_t* Al = sm4 + FM_AL;
    float4*   abc = (float4*)(sm4 + FM_ABC);
    int t = threadIdx.x, lane = t & 31, wid = t >> 5;
    int g = lane >> 2, tid = lane & 3;
    const uint32_t* wh = (const uint32_t*)g_W1h2;
    const uint32_t* wl = (const uint32_t*)g_W1l2;
    for (int i = t; i < 512*32; i += 256) {
        int n = i >> 5, k2 = i & 31;
        int j = fragperm(k2);
        Bh[n*36 + j] = wh[i];
        Bl[n*36 + j] = wl[i];
    }
    for (int i = t; i < 512; i += 256) abc[i] = g_abc[i];
    float bb = b2[0];
    int r0 = wid*16 + g;

    for (int tile = blockIdx.x; tile < NT/128; tile += gridDim.x) {
        int row0 = tile << 7;
        __syncthreads();
        const uint32_t* zh = (const uint32_t*)g_zrh2 + row0*32;
        const uint32_t* zl = (const uint32_t*)g_zrl2 + row0*32;
        for (int i = t; i < 128*32; i += 256) {
            int r = i >> 5, k2 = i & 31;
            int j = fragperm(k2);
            Ah[r*36 + j] = zh[i];
            Al[r*36 + j] = zl[i];
        }
        __syncthreads();
        uint4 qh0 = *(const uint4*)&Ah[r0*36 + tid*8];
        uint4 qh1 = *(const uint4*)&Ah[r0*36 + tid*8 + 4];
        uint4 qh2 = *(const uint4*)&Ah[(r0+8)*36 + tid*8];
        uint4 qh3 = *(const uint4*)&Ah[(r0+8)*36 + tid*8 + 4];
        uint4 ql0 = *(const uint4*)&Al[r0*36 + tid*8];
        uint4 ql1 = *(const uint4*)&Al[r0*36 + tid*8 + 4];
        uint4 ql2 = *(const uint4*)&Al[(r0+8)*36 + tid*8];
        uint4 ql3 = *(const uint4*)&Al[(r0+8)*36 + tid*8 + 4];
        uint32_t ah[4][4] = {
            {qh0.x, qh2.x, qh0.y, qh2.y}, {qh0.z, qh2.z, qh0.w, qh2.w},
            {qh1.x, qh3.x, qh1.y, qh3.y}, {qh1.z, qh3.z, qh1.w, qh3.w}};
        uint32_t al[4][4] = {
            {ql0.x, ql2.x, ql0.y, ql2.y}, {ql0.z, ql2.z, ql0.w, ql2.w},
            {ql1.x, ql3.x, ql1.y, ql3.y}, {ql1.z, ql3.z, ql1.w, ql3.w}};
        float part0 = 0.f, part1 = 0.f;
        #pragma unroll 2
        for (int nt = 0; nt < 64; nt++) {
            int nb = (nt*8 + g)*36 + tid*8;
            uint4 bh0 = *(const uint4*)&Bh[nb], bh1 = *(const uint4*)&Bh[nb+4];
            uint4 bl0 = *(const uint4*)&Bl[nb], bl1 = *(const uint4*)&Bl[nb+4];
            float hh[4]={0,0,0,0}, hl[4]={0,0,0,0}, lh[4]={0,0,0,0};
            mma16816(hh, ah[0], bh0.x, bh0.y); mma16816(hh, ah[1], bh0.z, bh0.w);
            mma16816(hh, ah[2], bh1.x, bh1.y); mma16816(hh, ah[3], bh1.z, bh1.w);
            mma16816(hl, ah[0], bl0.x, bl0.y); mma16816(hl, ah[1], bl0.z, bl0.w);
            mma16816(hl, ah[2], bl1.x, bl1.y); mma16816(hl, ah[3], bl1.z, bl1.w);
            mma16816(lh, al[0], bh0.x, bh0.y); mma16816(lh, al[1], bh0.z, bh0.w);
            mma16816(lh, al[2], bh1.x, bh1.y); mma16816(lh, al[3], bh1.z, bh1.w);
            float4 p0 = abc[nt*8 + tid*2];
            float4 p1 = abc[nt*8 + tid*2 + 1];
            float y;
            y = fmaxf(fmaf(hh[0]+hl[0]+lh[0], p0.x, p0.y), 0.f); part0 = fmaf(y, p0.z, part0);
            y = fmaxf(fmaf(hh[1]+hl[1]+lh[1], p1.x, p1.y), 0.f); part0 = fmaf(y, p1.z, part0);
            y = fmaxf(fmaf(hh[2]+hl[2]+lh[2], p0.x, p0.y), 0.f); part1 = fmaf(y, p0.z, part1);
            y = fmaxf(fmaf(hh[3]+hl[3]+lh[3], p1.x, p1.y), 0.f); part1 = fmaf(y, p1.z, part1);
        }
        part0 += __shfl_xor_sync(0xffffffffu, part0, 1);
        part0 += __shfl_xor_sync(0xffffffffu, part0, 2);
        part1 += __shfl_xor_sync(0xffffffffu, part1, 1);
        part1 += __shfl_xor_sync(0xffffffffu, part1, 2);
        if (tid == 0) {
            out[row0 + r0]     = part0 + bb;
            out[row0 + r0 + 8] = part1 + bb;
        }
    }
}

// ---------------- launch ----------------
extern "C" void kernel_launch(void* const* d_in, const int* in_sizes, int n_in,
                              void* d_out, int out_size) {
    const float* data     = (const float*)d_in[0];
    const float* W_emb    = (const float*)d_in[2];
    const float* W_lin    = (const float*)d_in[3];
    const float* att_i    = (const float*)d_in[4];
    const float* att_j    = (const float*)d_in[5];
    const float* att_em_i = (const float*)d_in[6];
    const float* att_em_j = (const float*)d_in[7];
    const float* b_gnn    = (const float*)d_in[8];
    const float* gbn1     = (const float*)d_in[9];
    const float* bbn1     = (const float*)d_in[10];
    const float* gbn2     = (const float*)d_in[11];
    const float* bbn2     = (const float*)d_in[12];
    const float* W1       = (const float*)d_in[13];
    const float* b1       = (const float*)d_in[14];
    const float* gbn3     = (const float*)d_in[15];
    const float* bbn3     = (const float*)d_in[16];
    const float* W2       = (const float*)d_in[17];
    const float* b2       = (const float*)d_in[18];
    float* out = (float*)d_out;

    cudaFuncSetAttribute(k_xl_mma,    cudaFuncAttributeMaxDynamicSharedMemorySize, SMEM_XL);
    cudaFuncSetAttribute(k_agg,       cudaFuncAttributeMaxDynamicSharedMemorySize, SMEM_AGG);
    cudaFuncSetAttribute(k_final_mma, cudaFuncAttributeMaxDynamicSharedMemorySize, SMEM_FM);
    int nsm = 0;
    cudaDeviceGetAttribute(&nsm, cudaDevAttrMultiProcessorCount, 0);
    if (nsm <= 0) nsm = 148;

    k_prep<<<2, 512>>>(W_emb, att_em_i, att_em_j);
    k_prepW1<<<32, 512>>>(W1);
    k_topk<<<NODE, 128>>>(W_emb);
    k_xl_mma<<<nsm*2, 256, SMEM_XL>>>(data, W_lin, att_i, att_j);
    k_agg<<<512, 256, SMEM_AGG>>>(b_gnn);
    k_bnfin<<<1, 64>>>(gbn1, bbn1, 0);
    k_hz2<<<1024, 256>>>(b_gnn, W_emb);
    k_bnfin<<<1, 64>>>(gbn2, bbn2, 1);
    k_zr<<<nsm, 256>>>(b_gnn, W_emb);
    k_bn3fin<<<16, 32>>>(W1, b1, gbn3, bbn3, W2);
    k_final_mma<<<nsm, 256, SMEM_FM>>>(b2, out);
}

// round 8
// speedup vs baseline: 1.6630x; 1.0353x over previous
#include <cuda_runtime.h>
#include <cuda_bf16.h>
#include <math.h>
#include <stdint.h>

#define BATCH 256
#define NODE  512
#define WIN   64
#define EMB   64
#define TOPK  16
#define INTER 512
#define NT    (BATCH*NODE)     /* 131072 */
#define NEG   0.2f
#define EPS   1e-5f

// ---------------- scratch (static device globals) ----------------
__device__ float g_xl[NT*EMB];
__device__ float g_agg[NT*EMB];
__device__ __align__(16) uint32_t g_zrh[NT*EMB/2];   // bf16x2, fragperm word order
__device__ __align__(16) uint32_t g_zrl[NT*EMB/2];
__device__ __align__(16) uint32_t g_W1h[INTER*EMB/2]; // fragperm word order
__device__ __align__(16) uint32_t g_W1l[INTER*EMB/2];
__device__ float g_si[NT];
__device__ float g_sj[NT];
__device__ int   g_topk[NODE*TOPK];
__device__ float g_ei[NODE], g_ej[NODE], g_inv[NODE];
// [0:64]=bn1 sum  [64:128]=bn1 sq  [128:192]=bn2 sum [192:256]=bn2 sq
// [256:320]=zr colsum  [320:4416]=M2 (64x64 second moment of zr)
__device__ float g_stats[4416];
__device__ float g_sc1[EMB], g_sh1[EMB], g_sc2[EMB], g_sh2[EMB];
__device__ float4 g_abc[INTER];   // {bn3_scale, bn3_shift, W2, 0}

// ---------------- HMMA helper ----------------
__device__ __forceinline__ void mma16816(float* d, const uint32_t* a, uint32_t b0, uint32_t b1) {
    asm volatile("mma.sync.aligned.m16n8k16.row.col.f32.bf16.bf16.f32 "
        "{%0,%1,%2,%3}, {%4,%5,%6,%7}, {%8,%9}, {%0,%1,%2,%3};"
        : "+f"(d[0]), "+f"(d[1]), "+f"(d[2]), "+f"(d[3])
        : "r"(a[0]), "r"(a[1]), "r"(a[2]), "r"(a[3]), "r"(b0), "r"(b1));
}
// fragment-order permutation of a 32-word (64 bf16) k-row:
// j = tid*8 + ks*2 + h   (tid=k2&3, h=(k2>>2)&1, ks=k2>>3)
__device__ __forceinline__ int fragperm(int k2) {
    return (k2 & 3)*8 + (k2 >> 3)*2 + ((k2 >> 2) & 1);
}
__device__ __forceinline__ uint32_t packsplit(float x, float y, uint32_t* lo) {
    __nv_bfloat16 h0 = __float2bfloat16(x);
    __nv_bfloat16 h1 = __float2bfloat16(y);
    __nv_bfloat162 l2 = __halves2bfloat162(__float2bfloat16(x - __bfloat162float(h0)),
                                           __float2bfloat16(y - __bfloat162float(h1)));
    *lo = *(uint32_t*)&l2;
    __nv_bfloat162 h2 = __halves2bfloat162(h0, h1);
    return *(uint32_t*)&h2;
}

// ---------------- prep: zero stats + out; per-node embedding dots + inv norms ----------------
__global__ void k_prep(const float* __restrict__ W_emb,
                       const float* __restrict__ aei,
                       const float* __restrict__ aej,
                       float* __restrict__ out) {
    int t = threadIdx.x, b = blockIdx.x;
    if (b == 0) {
        for (int i = t; i < 4416; i += blockDim.x) g_stats[i] = 0.f;
    } else if (b == 1) {
        int v = t;
        const float* w = W_emb + v*EMB;
        float di = 0.f, dj = 0.f, nn = 0.f;
        #pragma unroll
        for (int k = 0; k < EMB; k++) {
            float x = w[k];
            di += x*aei[k]; dj += x*aej[k]; nn += x*x;
        }
        g_ei[v] = di; g_ej[v] = dj; g_inv[v] = rsqrtf(nn);
    } else {
        // zero out (needed: k_final accumulates with atomics)
        float4* o4 = (float4*)out;
        int idx = (b - 2)*512 + t;              // 64 blocks * 512 threads = 32768 float4
        o4[idx] = make_float4(0.f, 0.f, 0.f, 0.f);
    }
}

// ---------------- W1 -> bf16 hi/lo (fragperm word order) ----------------
__global__ void k_prepW1(const float* __restrict__ W1) {
    int i = blockIdx.x*512 + threadIdx.x;
    if (i < INTER*EMB/2) {
        float2 w = ((const float2*)W1)[i];
        uint32_t lo, hi = packsplit(w.x, w.y, &lo);
        int n = i >> 5, k2 = i & 31;
        int j = n*32 + fragperm(k2);
        g_W1h[j] = hi;
        g_W1l[j] = lo;
    }
}

// ---------------- cosine-similarity top-k (one block per node) ----------------
__global__ void k_topk(const float* __restrict__ W_emb) {
    __shared__ float wi[64];
    __shared__ float cosv[NODE];
    __shared__ float rv[128];
    __shared__ int   ri[128];
    int i = blockIdx.x, t = threadIdx.x;
    if (t < 64) wi[t] = W_emb[i*64 + t];
    __syncthreads();
    float inv_i = g_inv[i];
    for (int j = t; j < NODE; j += 128) {
        const float4* wj = (const float4*)&W_emb[j*64];
        float d = 0.f;
        #pragma unroll
        for (int kk = 0; kk < 16; kk++) {
            float4 b = wj[kk];
            d += wi[kk*4+0]*b.x + wi[kk*4+1]*b.y + wi[kk*4+2]*b.z + wi[kk*4+3]*b.w;
        }
        cosv[j] = d * inv_i * g_inv[j];
    }
    __syncthreads();
    for (int s = 0; s < TOPK; s++) {
        float bv = -3e38f; int bi = NODE;
        for (int j = t; j < NODE; j += 128) {
            float v = cosv[j];
            if (v > bv || (v == bv && j < bi)) { bv = v; bi = j; }
        }
        rv[t] = bv; ri[t] = bi;
        __syncthreads();
        for (int off = 64; off > 0; off >>= 1) {
            if (t < off) {
                float v2 = rv[t+off]; int i2 = ri[t+off];
                if (v2 > rv[t] || (v2 == rv[t] && i2 < ri[t])) { rv[t] = v2; ri[t] = i2; }
            }
            __syncthreads();
        }
        if (t == 0) { g_topk[i*TOPK + s] = ri[0]; cosv[ri[0]] = -3e38f; }
        __syncthreads();
    }
}

// ---------------- xl = x @ W_lin^T via HMMA split + fused attention scores ----------------
#define XL_BH 0
#define XL_BL 2304
#define XL_AH 4608
#define XL_AL 9216
#define XL_AI 13824
#define XL_AJ 13888
#define SMEM_XL (13952*4)
__global__ void __launch_bounds__(256, 2)
k_xl_mma(const float* __restrict__ x, const float* __restrict__ W_lin,
         const float* __restrict__ att_i, const float* __restrict__ att_j) {
    extern __shared__ uint32_t smx[];
    uint32_t* Bh = smx + XL_BH;
    uint32_t* Bl = smx + XL_BL;
    uint32_t* Ah = smx + XL_AH;
    uint32_t* Al = smx + XL_AL;
    float* ai = (float*)(smx + XL_AI);
    float* aj = (float*)(smx + XL_AJ);
    int t = threadIdx.x, lane = t & 31, wid = t >> 5;
    int g = lane >> 2, tid = lane & 3;
    for (int i = t; i < 64*32; i += 256) {
        int e = i >> 5, k2 = i & 31;
        float2 w = ((const float2*)W_lin)[i];
        uint32_t lo, hi = packsplit(w.x, w.y, &lo);
        int j = fragperm(k2);
        Bh[e*36 + j] = hi; Bl[e*36 + j] = lo;
    }
    if (t < 64) { ai[t] = att_i[t]; aj[t] = att_j[t]; }
    int r0 = wid*16 + g;
    for (int tile = blockIdx.x; tile < NT/128; tile += gridDim.x) {
        int row0 = tile << 7;
        __syncthreads();
        for (int i = t; i < 128*32; i += 256) {
            int r = i >> 5, k2 = i & 31;
            float2 v = ((const float2*)x)[row0*32 + i];
            uint32_t lo, hi = packsplit(v.x, v.y, &lo);
            int j = fragperm(k2);
            Ah[r*36 + j] = hi; Al[r*36 + j] = lo;
        }
        __syncthreads();
        uint4 qh0 = *(const uint4*)&Ah[r0*36 + tid*8];
        uint4 qh1 = *(const uint4*)&Ah[r0*36 + tid*8 + 4];
        uint4 qh2 = *(const uint4*)&Ah[(r0+8)*36 + tid*8];
        uint4 qh3 = *(const uint4*)&Ah[(r0+8)*36 + tid*8 + 4];
        uint4 ql0 = *(const uint4*)&Al[r0*36 + tid*8];
        uint4 ql1 = *(const uint4*)&Al[r0*36 + tid*8 + 4];
        uint4 ql2 = *(const uint4*)&Al[(r0+8)*36 + tid*8];
        uint4 ql3 = *(const uint4*)&Al[(r0+8)*36 + tid*8 + 4];
        uint32_t ah[4][4] = {
            {qh0.x, qh2.x, qh0.y, qh2.y}, {qh0.z, qh2.z, qh0.w, qh2.w},
            {qh1.x, qh3.x, qh1.y, qh3.y}, {qh1.z, qh3.z, qh1.w, qh3.w}};
        uint32_t al[4][4] = {
            {ql0.x, ql2.x, ql0.y, ql2.y}, {ql0.z, ql2.z, ql0.w, ql2.w},
            {ql1.x, ql3.x, ql1.y, ql3.y}, {ql1.z, ql3.z, ql1.w, ql3.w}};
        float pi0=0, pi1=0, pj0=0, pj1=0;
        #pragma unroll
        for (int nt = 0; nt < 8; nt++) {
            int nb = (nt*8 + g)*36 + tid*8;
            uint4 bh0 = *(const uint4*)&Bh[nb], bh1 = *(const uint4*)&Bh[nb+4];
            uint4 bl0 = *(const uint4*)&Bl[nb], bl1 = *(const uint4*)&Bl[nb+4];
            float hh[4]={0,0,0,0}, hl[4]={0,0,0,0}, lh[4]={0,0,0,0};
            mma16816(hh, ah[0], bh0.x, bh0.y); mma16816(hh, ah[1], bh0.z, bh0.w);
            mma16816(hh, ah[2], bh1.x, bh1.y); mma16816(hh, ah[3], bh1.z, bh1.w);
            mma16816(hl, ah[0], bl0.x, bl0.y); mma16816(hl, ah[1], bl0.z, bl0.w);
            mma16816(hl, ah[2], bl1.x, bl1.y); mma16816(hl, ah[3], bl1.z, bl1.w);
            mma16816(lh, al[0], bh0.x, bh0.y); mma16816(lh, al[1], bh0.z, bh0.w);
            mma16816(lh, al[2], bh1.x, bh1.y); mma16816(lh, al[3], bh1.z, bh1.w);
            float v0 = hh[0]+hl[0]+lh[0], v1 = hh[1]+hl[1]+lh[1];
            float v2 = hh[2]+hl[2]+lh[2], v3 = hh[3]+hl[3]+lh[3];
            int col = nt*8 + tid*2;
            *(float2*)&g_xl[(row0+r0)*64 + col]   = make_float2(v0, v1);
            *(float2*)&g_xl[(row0+r0+8)*64 + col] = make_float2(v2, v3);
            float a0 = ai[col], a1 = ai[col+1], j0 = aj[col], j1 = aj[col+1];
            pi0 += v0*a0 + v1*a1;  pj0 += v0*j0 + v1*j1;
            pi1 += v2*a0 + v3*a1;  pj1 += v2*j0 + v3*j1;
        }
        pi0 += __shfl_xor_sync(0xffffffffu, pi0, 1); pi0 += __shfl_xor_sync(0xffffffffu, pi0, 2);
        pj0 += __shfl_xor_sync(0xffffffffu, pj0, 1); pj0 += __shfl_xor_sync(0xffffffffu, pj0, 2);
        pi1 += __shfl_xor_sync(0xffffffffu, pi1, 1); pi1 += __shfl_xor_sync(0xffffffffu, pi1, 2);
        pj1 += __shfl_xor_sync(0xffffffffu, pj1, 1); pj1 += __shfl_xor_sync(0xffffffffu, pj1, 2);
        if (tid == 0) {
            int n0 = row0 + r0, v = n0 & (NODE-1);
            g_si[n0] = pi0 + g_ei[v]; g_sj[n0] = pj0 + g_ej[v];
            n0 += 8; v = n0 & (NODE-1);
            g_si[n0] = pi1 + g_ei[v]; g_sj[n0] = pj1 + g_ej[v];
        }
    }
}

// ---------------- GAT aggregation: smem-resident xl slab, LDS gather ----------------
#define AGG_XL   0
#define AGG_TK   16384
#define AGG_SI   24576
#define AGG_SJ   25088
#define AGG_W    25600
#define AGG_SS   25856
#define AGG_SQ   25888
#define SMEM_AGG ((25920)*4)
__global__ void __launch_bounds__(256, 2)
k_agg(const float* __restrict__ b_gnn) {
    extern __shared__ float smA[];
    float* sxl = smA + AGG_XL;
    int*   stk = (int*)(smA + AGG_TK);
    float* ssi = smA + AGG_SI;
    float* ssj = smA + AGG_SJ;
    float2* swp = (float2*)(smA + AGG_W);
    float* sms = smA + AGG_SS;
    float* smq = smA + AGG_SQ;
    int t = threadIdx.x, wid = t >> 5, lane = t & 31;
    int b = blockIdx.x >> 1, h = blockIdx.x & 1;
    const float4* src = (const float4*)&g_xl[b*NODE*EMB + h*32];
    for (int i = t; i < 512*8; i += 256) {
        int r = i >> 3, q = i & 7;
        ((float4*)sxl)[r*8 + q] = src[r*16 + q];
    }
    for (int i = t; i < NODE*TOPK; i += 256) stk[i] = g_topk[i];
    for (int i = t; i < NODE; i += 256) { ssi[i] = g_si[b*NODE + i]; ssj[i] = g_sj[b*NODE + i]; }
    if (t < 32) { sms[t] = 0.f; smq[t] = 0.f; }
    __syncthreads();
    int k = lane & 15;
    float bg = b_gnn[h*32 + lane];
    float s = 0.f, q = 0.f;
    float2* stage = swp + wid*16;
    for (int v = wid*64; v < wid*64 + 64; v++) {
        int nbr = stk[v*16 + k];
        float a = ssi[v] + ssj[nbr];
        a = a > 0.f ? a : NEG*a;
        float m = a;
        #pragma unroll
        for (int o = 8; o > 0; o >>= 1) m = fmaxf(m, __shfl_xor_sync(0xffffffffu, m, o, 16));
        float ex = expf(a - m);
        float den = ex;
        #pragma unroll
        for (int o = 8; o > 0; o >>= 1) den += __shfl_xor_sync(0xffffffffu, den, o, 16);
        float w = ex / den;
        if (lane < 16) stage[lane] = make_float2(w, __int_as_float(nbr));
        __syncwarp();
        float acc = 0.f;
        #pragma unroll
        for (int kk = 0; kk < 16; kk++) {
            float2 p = stage[kk];
            acc += p.x * sxl[__float_as_int(p.y)*32 + lane];
        }
        g_agg[(b*NODE + v)*EMB + h*32 + lane] = acc;
        float z = acc + bg;
        s += z; q += z*z;
        __syncwarp();
    }
    atomicAdd(&sms[lane], s);
    atomicAdd(&smq[lane], q);
    __syncthreads();
    if (t < 32) {
        atomicAdd(&g_stats[h*32 + t],      sms[t]);
        atomicAdd(&g_stats[64 + h*32 + t], smq[t]);
    }
}

// ---------------- finalize bn1/bn2 ----------------
__global__ void k_bnfin(const float* __restrict__ gamma, const float* __restrict__ beta, int which) {
    int c = threadIdx.x;
    if (c >= EMB) return;
    float s = g_stats[which*128 + c], q = g_stats[which*128 + 64 + c];
    float m = s * (1.f/NT);
    float v = q * (1.f/NT) - m*m;
    float sc = gamma[c] * rsqrtf(v + EPS);
    float sh = beta[c] - m*sc;
    if (which == 0) { g_sc1[c] = sc; g_sh1[c] = sh; }
    else            { g_sc2[c] = sc; g_sh2[c] = sh; }
}

// ---------------- bn2 stats from agg (no z materialization) ----------------
__global__ void k_hz2(const float* __restrict__ b_gnn, const float* __restrict__ W_emb) {
    __shared__ float sm_s[64], sm_q[64];
    int t = threadIdx.x;
    if (t < 64) { sm_s[t] = 0.f; sm_q[t] = 0.f; }
    __syncthreads();
    int gt = blockIdx.x*256 + t;
    int c0 = (gt & 31)*2;
    float A0 = g_sc1[c0], A1 = g_sc1[c0+1];
    float B0 = fmaf(b_gnn[c0],   A0, g_sh1[c0]);
    float B1 = fmaf(b_gnn[c0+1], A1, g_sh1[c0+1]);
    float s0=0,q0=0,s1=0,q1=0;
    const float2* a2 = (const float2*)g_agg;
    const int stride = 1024*256;
    for (int idx = gt; idx < NT*32; idx += stride) {
        int row = idx >> 5;
        int v = row & (NODE-1);
        float2 a = a2[idx];
        float h0 = fmaxf(fmaf(a.x, A0, B0), 0.f);
        float h1 = fmaxf(fmaf(a.y, A1, B1), 0.f);
        float2 we = *(const float2*)&W_emb[v*EMB + c0];
        float z0 = h0 * we.x;
        float z1 = h1 * we.y;
        s0 += z0; q0 += z0*z0; s1 += z1; q1 += z1*z1;
    }
    atomicAdd(&sm_s[c0],   s0); atomicAdd(&sm_q[c0],   q0);
    atomicAdd(&sm_s[c0+1], s1); atomicAdd(&sm_q[c0+1], q1);
    __syncthreads();
    if (t < 64) { atomicAdd(&g_stats[128+t], sm_s[t]); atomicAdd(&g_stats[192+t], sm_q[t]); }
}

// ---------------- zr from agg; emit bf16 hi/lo (fragperm order); SYRK + colsum ----------------
__global__ void __launch_bounds__(256, 1)
k_zr(const float* __restrict__ b_gnn, const float* __restrict__ W_emb) {
    __shared__ float zs[128*68];
    __shared__ float cA[64], cB[64], c2s[64], c2h[64];
    __shared__ float red[256];
    int t = threadIdx.x;
    if (t < 64) {
        float sc = g_sc1[t];
        cA[t] = sc;
        cB[t] = fmaf(b_gnn[t], sc, g_sh1[t]);
        c2s[t] = g_sc2[t]; c2h[t] = g_sh2[t];
    }
    int tx = t & 15, ty = t >> 4;
    int a0 = ty*4, b0 = tx*4;
    float acc[4][4];
    #pragma unroll
    for (int i = 0; i < 4; i++)
        #pragma unroll
        for (int j = 0; j < 4; j++) acc[i][j] = 0.f;
    float csum = 0.f;
    int cc = t & 63, rr0 = t >> 6;
    for (int tile = blockIdx.x; tile < NT/128; tile += gridDim.x) {
        int row0 = tile << 7;
        __syncthreads();
        for (int i = t; i < 128*32; i += 256) {
            int r = i >> 5, k2 = i & 31, c0 = k2*2;
            int v = (row0 + r) & (NODE-1);
            float2 a = ((const float2*)g_agg)[row0*32 + i];
            float2 we = *(const float2*)&W_emb[v*EMB + c0];
            float h0 = fmaxf(fmaf(a.x, cA[c0],   cB[c0]),   0.f);
            float h1 = fmaxf(fmaf(a.y, cA[c0+1], cB[c0+1]), 0.f);
            float z0 = fmaxf(fmaf(h0*we.x, c2s[c0],   c2h[c0]),   0.f);
            float z1 = fmaxf(fmaf(h1*we.y, c2s[c0+1], c2h[c0+1]), 0.f);
            zs[r*68 + c0] = z0; zs[r*68 + c0 + 1] = z1;
            uint32_t lo, hi = packsplit(z0, z1, &lo);
            int j = (row0 + r)*32 + fragperm(k2);
            g_zrh[j] = hi;
            g_zrl[j] = lo;
        }
        __syncthreads();
        for (int r = rr0; r < 128; r += 4) csum += zs[r*68 + cc];
        #pragma unroll 4
        for (int r = 0; r < 128; r++) {
            float4 va = *(const float4*)&zs[r*68 + a0];
            float4 vb = *(const float4*)&zs[r*68 + b0];
            float av[4] = {va.x, va.y, va.z, va.w};
            float bv[4] = {vb.x, vb.y, vb.z, vb.w};
            #pragma unroll
            for (int i = 0; i < 4; i++)
                #pragma unroll
                for (int j = 0; j < 4; j++) acc[i][j] += av[i]*bv[j];
        }
    }
    __syncthreads();
    red[t] = csum;
    __syncthreads();
    if (t < 64) atomicAdd(&g_stats[256 + t], red[t] + red[64+t] + red[128+t] + red[192+t]);
    #pragma unroll
    for (int i = 0; i < 4; i++)
        #pragma unroll
        for (int j = 0; j < 4; j++)
            atomicAdd(&g_stats[320 + (a0+i)*64 + b0 + j], acc[i][j]);
}

// ---------------- analytic BN3: pack {sc,sh,w2} ----------------
__global__ void k_bn3fin(const float* __restrict__ W1, const float* __restrict__ b1,
                         const float* __restrict__ g3, const float* __restrict__ b3,
                         const float* __restrict__ W2) {
    __shared__ float Cov[EMB*EMB];
    __shared__ float zb[EMB];
    int t = threadIdx.x;
    for (int i = t; i < EMB; i += 32) zb[i] = g_stats[256+i] * (1.f/NT);
    __syncthreads();
    for (int i = t; i < EMB*EMB; i += 32)
        Cov[i] = g_stats[320+i] * (1.f/NT) - zb[i >> 6]*zb[i & 63];
    __syncthreads();
    int c = blockIdx.x*32 + t;
    const float* wc = W1 + c*EMB;
    float wr[EMB];
    #pragma unroll
    for (int k = 0; k < EMB; k++) wr[k] = wc[k];
    float m = b1[c];
    #pragma unroll
    for (int k = 0; k < EMB; k++) m += zb[k]*wr[k];
    float var = 0.f;
    for (int a = 0; a < EMB; a++) {
        float ta = 0.f;
        #pragma unroll 8
        for (int b = 0; b < EMB; b++) ta += Cov[a*EMB + b]*wr[b];
        var += ta * wr[a];
    }
    float sc = g3[c] * rsqrtf(var + EPS);
    g_abc[c] = make_float4(sc, b3[c] - m*sc, W2[c], 0.f);
}

// ---------------- final: split-N HMMA GEMM, A direct from gmem, atomic output ----------------
// smem (words): Bh[256*36], Bl[256*36], abc float4[256]
#define F2_BH  0
#define F2_BL  9216
#define F2_ABC 18432
#define SMEM_F2 ((18432 + 1024)*4)   /* 77824 B -> 2 CTAs/SM */

__global__ void __launch_bounds__(256, 2)
k_final_mma(const float* __restrict__ b2, float* __restrict__ out) {
    extern __shared__ uint32_t sm4[];
    uint32_t* Bh = sm4 + F2_BH;
    uint32_t* Bl = sm4 + F2_BL;
    float4*   abc = (float4*)(sm4 + F2_ABC);
    int t = threadIdx.x, lane = t & 31, wid = t >> 5;
    int g = lane >> 2, tid = lane & 3;
    int half = blockIdx.x & 1;
    const uint32_t* wh = g_W1h + half*256*32;
    const uint32_t* wl = g_W1l + half*256*32;
    for (int i = t; i < 256*32; i += 256) {
        int n = i >> 5, k2 = i & 31;
        Bh[n*36 + k2] = wh[i];
        Bl[n*36 + k2] = wl[i];
    }
    for (int i = t; i < 256; i += 256) abc[i] = g_abc[half*256 + i];
    float bb = half ? 0.f : b2[0];
    __syncthreads();

    int tstep = gridDim.x >> 1;
    for (int tile = blockIdx.x >> 1; tile < NT/128; tile += tstep) {
        int row = (tile << 7) + wid*16 + g;
        const uint4* zh0 = (const uint4*)(g_zrh + row*32);
        const uint4* zl0 = (const uint4*)(g_zrl + row*32);
        // row stride = 32 words = 8 uint4, so row+8 => +64 uint4
        uint4 qh0 = zh0[tid*2],      qh1 = zh0[tid*2 + 1];
        uint4 qh2 = zh0[tid*2 + 64], qh3 = zh0[tid*2 + 65];
        uint4 ql0 = zl0[tid*2],      ql1 = zl0[tid*2 + 1];
        uint4 ql2 = zl0[tid*2 + 64], ql3 = zl0[tid*2 + 65];
        uint32_t ah[4][4] = {
            {qh0.x, qh2.x, qh0.y, qh2.y}, {qh0.z, qh2.z, qh0.w, qh2.w},
            {qh1.x, qh3.x, qh1.y, qh3.y}, {qh1.z, qh3.z, qh1.w, qh3.w}};
        uint32_t al[4][4] = {
            {ql0.x, ql2.x, ql0.y, ql2.y}, {ql0.z, ql2.z, ql0.w, ql2.w},
            {ql1.x, ql3.x, ql1.y, ql3.y}, {ql1.z, ql3.z, ql1.w, ql3.w}};
        float part0 = 0.f, part1 = 0.f;
        #pragma unroll 4
        for (int nt = 0; nt < 32; nt++) {
            int nb = (nt*8 + g)*36 + tid*8;
            uint4 bh0 = *(const uint4*)&Bh[nb], bh1 = *(const uint4*)&Bh[nb+4];
            uint4 bl0 = *(const uint4*)&Bl[nb], bl1 = *(const uint4*)&Bl[nb+4];
            float hh[4]={0,0,0,0}, hl[4]={0,0,0,0}, lh[4]={0,0,0,0};
            mma16816(hh, ah[0], bh0.x, bh0.y); mma16816(hh, ah[1], bh0.z, bh0.w);
            mma16816(hh, ah[2], bh1.x, bh1.y); mma16816(hh, ah[3], bh1.z, bh1.w);
            mma16816(hl, ah[0], bl0.x, bl0.y); mma16816(hl, ah[1], bl0.z, bl0.w);
            mma16816(hl, ah[2], bl1.x, bl1.y); mma16816(hl, ah[3], bl1.z, bl1.w);
            mma16816(lh, al[0], bh0.x, bh0.y); mma16816(lh, al[1], bh0.z, bh0.w);
            mma16816(lh, al[2], bh1.x, bh1.y); mma16816(lh, al[3], bh1.z, bh1.w);
            float4 p0 = abc[nt*8 + tid*2];
            float4 p1 = abc[nt*8 + tid*2 + 1];
            float y;
            y = fmaxf(fmaf(hh[0]+hl[0]+lh[0], p0.x, p0.y), 0.f); part0 = fmaf(y, p0.z, part0);
            y = fmaxf(fmaf(hh[1]+hl[1]+lh[1], p1.x, p1.y), 0.f); part0 = fmaf(y, p1.z, part0);
            y = fmaxf(fmaf(hh[2]+hl[2]+lh[2], p0.x, p0.y), 0.f); part1 = fmaf(y, p0.z, part1);
            y = fmaxf(fmaf(hh[3]+hl[3]+lh[3], p1.x, p1.y), 0.f); part1 = fmaf(y, p1.z, part1);
        }
        part0 += __shfl_xor_sync(0xffffffffu, part0, 1);
        part0 += __shfl_xor_sync(0xffffffffu, part0, 2);
        part1 += __shfl_xor_sync(0xffffffffu, part1, 1);
        part1 += __shfl_xor_sync(0xffffffffu, part1, 2);
        if (tid == 0) {
            atomicAdd(&out[row],     part0 + bb);
            atomicAdd(&out[row + 8], part1 + bb);
        }
    }
}

// ---------------- launch ----------------
extern "C" void kernel_launch(void* const* d_in, const int* in_sizes, int n_in,
                              void* d_out, int out_size) {
    const float* data     = (const float*)d_in[0];
    const float* W_emb    = (const float*)d_in[2];
    const float* W_lin    = (const float*)d_in[3];
    const float* att_i    = (const float*)d_in[4];
    const float* att_j    = (const float*)d_in[5];
    const float* att_em_i = (const float*)d_in[6];
    const float* att_em_j = (const float*)d_in[7];
    const float* b_gnn    = (const float*)d_in[8];
    const float* gbn1     = (const float*)d_in[9];
    const float* bbn1     = (const float*)d_in[10];
    const float* gbn2     = (const float*)d_in[11];
    const float* bbn2     = (const float*)d_in[12];
    const float* W1       = (const float*)d_in[13];
    const float* b1       = (const float*)d_in[14];
    const float* gbn3     = (const float*)d_in[15];
    const float* bbn3     = (const float*)d_in[16];
    const float* W2       = (const float*)d_in[17];
    const float* b2       = (const float*)d_in[18];
    float* out = (float*)d_out;

    cudaFuncSetAttribute(k_xl_mma,    cudaFuncAttributeMaxDynamicSharedMemorySize, SMEM_XL);
    cudaFuncSetAttribute(k_agg,       cudaFuncAttributeMaxDynamicSharedMemorySize, SMEM_AGG);
    cudaFuncSetAttribute(k_final_mma, cudaFuncAttributeMaxDynamicSharedMemorySize, SMEM_F2);
    int nsm = 0;
    cudaDeviceGetAttribute(&nsm, cudaDevAttrMultiProcessorCount, 0);
    if (nsm <= 0) nsm = 148;

    k_prep<<<2 + 64, 512>>>(W_emb, att_em_i, att_em_j, out);
    k_prepW1<<<32, 512>>>(W1);
    k_topk<<<NODE, 128>>>(W_emb);
    k_xl_mma<<<nsm*2, 256, SMEM_XL>>>(data, W_lin, att_i, att_j);
    k_agg<<<512, 256, SMEM_AGG>>>(b_gnn);
    k_bnfin<<<1, 64>>>(gbn1, bbn1, 0);
    k_hz2<<<1024, 256>>>(b_gnn, W_emb);
    k_bnfin<<<1, 64>>>(gbn2, bbn2, 1);
    k_zr<<<nsm, 256>>>(b_gnn, W_emb);
    k_bn3fin<<<16, 32>>>(W1, b1, gbn3, bbn3, W2);
    k_final_mma<<<nsm*2, 256, SMEM_F2>>>(b2, out);
}

// round 10
// speedup vs baseline: 1.7218x; 1.0354x over previous
#include <cuda_runtime.h>
#include <cuda_bf16.h>
#include <math.h>
#include <stdint.h>

#define BATCH 256
#define NODE  512
#define WIN   64
#define EMB   64
#define TOPK  16
#define INTER 512
#define NT    (BATCH*NODE)     /* 131072 */
#define NEG   0.2f
#define EPS   1e-5f

// ---------------- scratch (static device globals) ----------------
__device__ float g_xl[NT*EMB];
__device__ float g_agg[NT*EMB];
__device__ __align__(16) uint32_t g_zrh[NT*EMB/2];   // bf16x2, fragperm word order
__device__ __align__(16) uint32_t g_zrl[NT*EMB/2];
__device__ __align__(16) uint32_t g_W1h[INTER*EMB/2]; // fragperm word order
__device__ __align__(16) uint32_t g_W1l[INTER*EMB/2];
__device__ float g_si[NT];
__device__ float g_sj[NT];
__device__ int   g_topk[NODE*TOPK];
__device__ float g_ei[NODE], g_ej[NODE], g_inv[NODE];
// [0:64]=bn1 sum  [64:128]=bn1 sq  [128:192]=bn2 sum [192:256]=bn2 sq
// [256:320]=zr colsum  [320:4416]=M2 (64x64 second moment of zr)
__device__ float g_stats[4416];
__device__ float4 g_abc[INTER];   // {bn3_scale, bn3_shift, W2, 0}

// ---------------- HMMA helper ----------------
__device__ __forceinline__ void mma16816(float* d, const uint32_t* a, uint32_t b0, uint32_t b1) {
    asm volatile("mma.sync.aligned.m16n8k16.row.col.f32.bf16.bf16.f32 "
        "{%0,%1,%2,%3}, {%4,%5,%6,%7}, {%8,%9}, {%0,%1,%2,%3};"
        : "+f"(d[0]), "+f"(d[1]), "+f"(d[2]), "+f"(d[3])
        : "r"(a[0]), "r"(a[1]), "r"(a[2]), "r"(a[3]), "r"(b0), "r"(b1));
}
// fragment-order permutation of a 32-word (64 bf16) k-row
__device__ __forceinline__ int fragperm(int k2) {
    return (k2 & 3)*8 + (k2 >> 3)*2 + ((k2 >> 2) & 1);
}
__device__ __forceinline__ uint32_t packsplit(float x, float y, uint32_t* lo) {
    __nv_bfloat16 h0 = __float2bfloat16(x);
    __nv_bfloat16 h1 = __float2bfloat16(y);
    __nv_bfloat162 l2 = __halves2bfloat162(__float2bfloat16(x - __bfloat162float(h0)),
                                           __float2bfloat16(y - __bfloat162float(h1)));
    *lo = *(uint32_t*)&l2;
    __nv_bfloat162 h2 = __halves2bfloat162(h0, h1);
    return *(uint32_t*)&h2;
}

// ---------------- prep: zero stats + out; embed dots/norms; W1 hi/lo ----------------
__global__ void k_prep(const float* __restrict__ W_emb,
                       const float* __restrict__ aei,
                       const float* __restrict__ aej,
                       const float* __restrict__ W1,
                       float* __restrict__ out) {
    int t = threadIdx.x, b = blockIdx.x;
    if (b == 0) {
        for (int i = t; i < 4416; i += blockDim.x) g_stats[i] = 0.f;
    } else if (b == 1) {
        int v = t;
        const float* w = W_emb + v*EMB;
        float di = 0.f, dj = 0.f, nn = 0.f;
        #pragma unroll
        for (int k = 0; k < EMB; k++) {
            float x = w[k];
            di += x*aei[k]; dj += x*aej[k]; nn += x*x;
        }
        g_ei[v] = di; g_ej[v] = dj; g_inv[v] = rsqrtf(nn);
    } else if (b < 66) {
        float4* o4 = (float4*)out;
        int idx = (b - 2)*512 + t;              // 64 blocks * 512 threads = 32768 float4
        o4[idx] = make_float4(0.f, 0.f, 0.f, 0.f);
    } else {
        int i = (b - 66)*512 + t;               // 32 blocks: W1 split
        if (i < INTER*EMB/2) {
            float2 w = ((const float2*)W1)[i];
            uint32_t lo, hi = packsplit(w.x, w.y, &lo);
            int n = i >> 5, k2 = i & 31;
            int j = n*32 + fragperm(k2);
            g_W1h[j] = hi;
            g_W1l[j] = lo;
        }
    }
}

// ---------------- cosine-similarity top-k: one WARP per node, no barriers ----------------
__global__ void k_topk(const float* __restrict__ W_emb) {
    int t = threadIdx.x, lane = t & 31, w = t >> 5;
    int i = blockIdx.x*8 + w;   // node
    float wi[64];
    const float4* wi4 = (const float4*)&W_emb[i*64];
    #pragma unroll
    for (int k = 0; k < 16; k++) {
        float4 v = wi4[k];
        wi[k*4] = v.x; wi[k*4+1] = v.y; wi[k*4+2] = v.z; wi[k*4+3] = v.w;
    }
    float inv_i = g_inv[i];
    float cosv[16]; int jidx[16];
    #pragma unroll
    for (int q = 0; q < 16; q++) {
        int j = lane + q*32;
        const float4* wj = (const float4*)&W_emb[j*64];
        float d = 0.f;
        #pragma unroll
        for (int kk = 0; kk < 16; kk++) {
            float4 b = wj[kk];
            d += wi[kk*4]*b.x + wi[kk*4+1]*b.y + wi[kk*4+2]*b.z + wi[kk*4+3]*b.w;
        }
        cosv[q] = d * inv_i * g_inv[j];
        jidx[q] = j;
    }
    for (int s = 0; s < TOPK; s++) {
        float bv = -3e38f; int bj = NODE;
        #pragma unroll
        for (int q = 0; q < 16; q++) {
            if (cosv[q] > bv || (cosv[q] == bv && jidx[q] < bj)) { bv = cosv[q]; bj = jidx[q]; }
        }
        #pragma unroll
        for (int o = 16; o > 0; o >>= 1) {
            float v2 = __shfl_xor_sync(0xffffffffu, bv, o);
            int  j2 = __shfl_xor_sync(0xffffffffu, bj, o);
            if (v2 > bv || (v2 == bv && j2 < bj)) { bv = v2; bj = j2; }
        }
        if (lane == (bj & 31)) {
            int qi = bj >> 5;
            #pragma unroll
            for (int q = 0; q < 16; q++) if (q == qi) cosv[q] = -3e38f;
        }
        if (lane == 0) g_topk[i*TOPK + s] = bj;
    }
}

// ---------------- xl = x @ W_lin^T via HMMA split + fused attention scores ----------------
#define XL_BH 0
#define XL_BL 2304
#define XL_AH 4608
#define XL_AL 9216
#define XL_AI 13824
#define XL_AJ 13888
#define SMEM_XL (13952*4)
__global__ void __launch_bounds__(256, 2)
k_xl_mma(const float* __restrict__ x, const float* __restrict__ W_lin,
         const float* __restrict__ att_i, const float* __restrict__ att_j) {
    extern __shared__ uint32_t smx[];
    uint32_t* Bh = smx + XL_BH;
    uint32_t* Bl = smx + XL_BL;
    uint32_t* Ah = smx + XL_AH;
    uint32_t* Al = smx + XL_AL;
    float* ai = (float*)(smx + XL_AI);
    float* aj = (float*)(smx + XL_AJ);
    int t = threadIdx.x, lane = t & 31, wid = t >> 5;
    int g = lane >> 2, tid = lane & 3;
    for (int i = t; i < 64*32; i += 256) {
        int e = i >> 5, k2 = i & 31;
        float2 w = ((const float2*)W_lin)[i];
        uint32_t lo, hi = packsplit(w.x, w.y, &lo);
        int j = fragperm(k2);
        Bh[e*36 + j] = hi; Bl[e*36 + j] = lo;
    }
    if (t < 64) { ai[t] = att_i[t]; aj[t] = att_j[t]; }
    int r0 = wid*16 + g;
    for (int tile = blockIdx.x; tile < NT/128; tile += gridDim.x) {
        int row0 = tile << 7;
        __syncthreads();
        for (int i = t; i < 128*32; i += 256) {
            int r = i >> 5, k2 = i & 31;
            float2 v = ((const float2*)x)[row0*32 + i];
            uint32_t lo, hi = packsplit(v.x, v.y, &lo);
            int j = fragperm(k2);
            Ah[r*36 + j] = hi; Al[r*36 + j] = lo;
        }
        __syncthreads();
        uint4 qh0 = *(const uint4*)&Ah[r0*36 + tid*8];
        uint4 qh1 = *(const uint4*)&Ah[r0*36 + tid*8 + 4];
        uint4 qh2 = *(const uint4*)&Ah[(r0+8)*36 + tid*8];
        uint4 qh3 = *(const uint4*)&Ah[(r0+8)*36 + tid*8 + 4];
        uint4 ql0 = *(const uint4*)&Al[r0*36 + tid*8];
        uint4 ql1 = *(const uint4*)&Al[r0*36 + tid*8 + 4];
        uint4 ql2 = *(const uint4*)&Al[(r0+8)*36 + tid*8];
        uint4 ql3 = *(const uint4*)&Al[(r0+8)*36 + tid*8 + 4];
        uint32_t ah[4][4] = {
            {qh0.x, qh2.x, qh0.y, qh2.y}, {qh0.z, qh2.z, qh0.w, qh2.w},
            {qh1.x, qh3.x, qh1.y, qh3.y}, {qh1.z, qh3.z, qh1.w, qh3.w}};
        uint32_t al[4][4] = {
            {ql0.x, ql2.x, ql0.y, ql2.y}, {ql0.z, ql2.z, ql0.w, ql2.w},
            {ql1.x, ql3.x, ql1.y, ql3.y}, {ql1.z, ql3.z, ql1.w, ql3.w}};
        float pi0=0, pi1=0, pj0=0, pj1=0;
        #pragma unroll
        for (int nt = 0; nt < 8; nt++) {
            int nb = (nt*8 + g)*36 + tid*8;
            uint4 bh0 = *(const uint4*)&Bh[nb], bh1 = *(const uint4*)&Bh[nb+4];
            uint4 bl0 = *(const uint4*)&Bl[nb], bl1 = *(const uint4*)&Bl[nb+4];
            float hh[4]={0,0,0,0}, hl[4]={0,0,0,0}, lh[4]={0,0,0,0};
            mma16816(hh, ah[0], bh0.x, bh0.y); mma16816(hh, ah[1], bh0.z, bh0.w);
            mma16816(hh, ah[2], bh1.x, bh1.y); mma16816(hh, ah[3], bh1.z, bh1.w);
            mma16816(hl, ah[0], bl0.x, bl0.y); mma16816(hl, ah[1], bl0.z, bl0.w);
            mma16816(hl, ah[2], bl1.x, bl1.y); mma16816(hl, ah[3], bl1.z, bl1.w);
            mma16816(lh, al[0], bh0.x, bh0.y); mma16816(lh, al[1], bh0.z, bh0.w);
            mma16816(lh, al[2], bh1.x, bh1.y); mma16816(lh, al[3], bh1.z, bh1.w);
            float v0 = hh[0]+hl[0]+lh[0], v1 = hh[1]+hl[1]+lh[1];
            float v2 = hh[2]+hl[2]+lh[2], v3 = hh[3]+hl[3]+lh[3];
            int col = nt*8 + tid*2;
            *(float2*)&g_xl[(row0+r0)*64 + col]   = make_float2(v0, v1);
            *(float2*)&g_xl[(row0+r0+8)*64 + col] = make_float2(v2, v3);
            float a0 = ai[col], a1 = ai[col+1], j0 = aj[col], j1 = aj[col+1];
            pi0 += v0*a0 + v1*a1;  pj0 += v0*j0 + v1*j1;
            pi1 += v2*a0 + v3*a1;  pj1 += v2*j0 + v3*j1;
        }
        pi0 += __shfl_xor_sync(0xffffffffu, pi0, 1); pi0 += __shfl_xor_sync(0xffffffffu, pi0, 2);
        pj0 += __shfl_xor_sync(0xffffffffu, pj0, 1); pj0 += __shfl_xor_sync(0xffffffffu, pj0, 2);
        pi1 += __shfl_xor_sync(0xffffffffu, pi1, 1); pi1 += __shfl_xor_sync(0xffffffffu, pi1, 2);
        pj1 += __shfl_xor_sync(0xffffffffu, pj1, 1); pj1 += __shfl_xor_sync(0xffffffffu, pj1, 2);
        if (tid == 0) {
            int n0 = row0 + r0, v = n0 & (NODE-1);
            g_si[n0] = pi0 + g_ei[v]; g_sj[n0] = pj0 + g_ej[v];
            n0 += 8; v = n0 & (NODE-1);
            g_si[n0] = pi1 + g_ei[v]; g_sj[n0] = pj1 + g_ej[v];
        }
    }
}

// ---------------- GAT aggregation: smem-resident xl slab, LDS gather ----------------
#define AGG_XL   0
#define AGG_TK   16384
#define AGG_SI   24576
#define AGG_SJ   25088
#define AGG_W    25600
#define AGG_SS   25856
#define AGG_SQ   25888
#define SMEM_AGG ((25920)*4)
__global__ void __launch_bounds__(256, 2)
k_agg(const float* __restrict__ b_gnn) {
    extern __shared__ float smA[];
    float* sxl = smA + AGG_XL;
    int*   stk = (int*)(smA + AGG_TK);
    float* ssi = smA + AGG_SI;
    float* ssj = smA + AGG_SJ;
    float2* swp = (float2*)(smA + AGG_W);
    float* sms = smA + AGG_SS;
    float* smq = smA + AGG_SQ;
    int t = threadIdx.x, wid = t >> 5, lane = t & 31;
    int b = blockIdx.x >> 1, h = blockIdx.x & 1;
    const float4* src = (const float4*)&g_xl[b*NODE*EMB + h*32];
    for (int i = t; i < 512*8; i += 256) {
        int r = i >> 3, q = i & 7;
        ((float4*)sxl)[r*8 + q] = src[r*16 + q];
    }
    for (int i = t; i < NODE*TOPK; i += 256) stk[i] = g_topk[i];
    for (int i = t; i < NODE; i += 256) { ssi[i] = g_si[b*NODE + i]; ssj[i] = g_sj[b*NODE + i]; }
    if (t < 32) { sms[t] = 0.f; smq[t] = 0.f; }
    __syncthreads();
    int k = lane & 15;
    float bg = b_gnn[h*32 + lane];
    float s = 0.f, q = 0.f;
    float2* stage = swp + wid*16;
    for (int v = wid*64; v < wid*64 + 64; v++) {
        int nbr = stk[v*16 + k];
        float a = ssi[v] + ssj[nbr];
        a = a > 0.f ? a : NEG*a;
        float m = a;
        #pragma unroll
        for (int o = 8; o > 0; o >>= 1) m = fmaxf(m, __shfl_xor_sync(0xffffffffu, m, o, 16));
        float ex = expf(a - m);
        float den = ex;
        #pragma unroll
        for (int o = 8; o > 0; o >>= 1) den += __shfl_xor_sync(0xffffffffu, den, o, 16);
        float w = ex / den;
        if (lane < 16) stage[lane] = make_float2(w, __int_as_float(nbr));
        __syncwarp();
        float acc = 0.f;
        #pragma unroll
        for (int kk = 0; kk < 16; kk++) {
            float2 p = stage[kk];
            acc += p.x * sxl[__float_as_int(p.y)*32 + lane];
        }
        g_agg[(b*NODE + v)*EMB + h*32 + lane] = acc;
        float z = acc + bg;
        s += z; q += z*z;
        __syncwarp();
    }
    atomicAdd(&sms[lane], s);
    atomicAdd(&smq[lane], q);
    __syncthreads();
    if (t < 32) {
        atomicAdd(&g_stats[h*32 + t],      sms[t]);
        atomicAdd(&g_stats[64 + h*32 + t], smq[t]);
    }
}

// ---------------- bn2 stats from agg (bn1 finalized inline from g_stats) ----------------
__global__ void k_hz2(const float* __restrict__ b_gnn, const float* __restrict__ W_emb,
                      const float* __restrict__ g1, const float* __restrict__ b1v) {
    __shared__ float sA[64], sB[64], sm_s[64], sm_q[64];
    int t = threadIdx.x;
    if (t < 64) {
        float s = g_stats[t], q = g_stats[64+t];
        float m = s * (1.f/NT);
        float v = q * (1.f/NT) - m*m;
        float sc = g1[t] * rsqrtf(v + EPS);
        sA[t] = sc;
        sB[t] = fmaf(b_gnn[t], sc, b1v[t] - m*sc);
        sm_s[t] = 0.f; sm_q[t] = 0.f;
    }
    __syncthreads();
    int gt = blockIdx.x*256 + t;
    int c0 = (gt & 31)*2;
    float A0 = sA[c0], A1 = sA[c0+1];
    float B0 = sB[c0], B1 = sB[c0+1];
    float s0=0,q0=0,s1=0,q1=0;
    const float2* a2 = (const float2*)g_agg;
    const int stride = 1024*256;
    for (int idx = gt; idx < NT*32; idx += stride) {
        int row = idx >> 5;
        int v = row & (NODE-1);
        float2 a = a2[idx];
        float h0 = fmaxf(fmaf(a.x, A0, B0), 0.f);
        float h1 = fmaxf(fmaf(a.y, A1, B1), 0.f);
        float2 we = *(const float2*)&W_emb[v*EMB + c0];
        float z0 = h0 * we.x;
        float z1 = h1 * we.y;
        s0 += z0; q0 += z0*z0; s1 += z1; q1 += z1*z1;
    }
    atomicAdd(&sm_s[c0],   s0); atomicAdd(&sm_q[c0],   q0);
    atomicAdd(&sm_s[c0+1], s1); atomicAdd(&sm_q[c0+1], q1);
    __syncthreads();
    if (t < 64) { atomicAdd(&g_stats[128+t], sm_s[t]); atomicAdd(&g_stats[192+t], sm_q[t]); }
}

// ---------------- zr from agg (bn1+bn2 inline); emit bf16 hi/lo; SYRK + colsum ----------------
__global__ void __launch_bounds__(256, 2)
k_zr(const float* __restrict__ b_gnn, const float* __restrict__ W_emb,
     const float* __restrict__ g1, const float* __restrict__ b1v,
     const float* __restrict__ g2, const float* __restrict__ b2v) {
    __shared__ float zs[128*68];
    __shared__ float cA[64], cB[64], c2s[64], c2h[64];
    __shared__ float red[256];
    int t = threadIdx.x;
    if (t < 64) {
        float s = g_stats[t], q = g_stats[64+t];
        float m = s * (1.f/NT);
        float v = q * (1.f/NT) - m*m;
        float sc = g1[t] * rsqrtf(v + EPS);
        cA[t] = sc;
        cB[t] = fmaf(b_gnn[t], sc, b1v[t] - m*sc);
        s = g_stats[128+t]; q = g_stats[192+t];
        m = s * (1.f/NT);
        v = q * (1.f/NT) - m*m;
        sc = g2[t] * rsqrtf(v + EPS);
        c2s[t] = sc;
        c2h[t] = b2v[t] - m*sc;
    }
    int tx = t & 15, ty = t >> 4;
    int a0 = ty*4, b0 = tx*4;
    float acc[4][4];
    #pragma unroll
    for (int i = 0; i < 4; i++)
        #pragma unroll
        for (int j = 0; j < 4; j++) acc[i][j] = 0.f;
    float csum = 0.f;
    int cc = t & 63, rr0 = t >> 6;
    for (int tile = blockIdx.x; tile < NT/128; tile += gridDim.x) {
        int row0 = tile << 7;
        __syncthreads();
        for (int i = t; i < 128*32; i += 256) {
            int r = i >> 5, k2 = i & 31, c0 = k2*2;
            int v = (row0 + r) & (NODE-1);
            float2 a = ((const float2*)g_agg)[row0*32 + i];
            float2 we = *(const float2*)&W_emb[v*EMB + c0];
            float h0 = fmaxf(fmaf(a.x, cA[c0],   cB[c0]),   0.f);
            float h1 = fmaxf(fmaf(a.y, cA[c0+1], cB[c0+1]), 0.f);
            float z0 = fmaxf(fmaf(h0*we.x, c2s[c0],   c2h[c0]),   0.f);
            float z1 = fmaxf(fmaf(h1*we.y, c2s[c0+1], c2h[c0+1]), 0.f);
            zs[r*68 + c0] = z0; zs[r*68 + c0 + 1] = z1;
            uint32_t lo, hi = packsplit(z0, z1, &lo);
            int j = (row0 + r)*32 + fragperm(k2);
            g_zrh[j] = hi;
            g_zrl[j] = lo;
        }
        __syncthreads();
        for (int r = rr0; r < 128; r += 4) csum += zs[r*68 + cc];
        #pragma unroll 4
        for (int r = 0; r < 128; r++) {
            float4 va = *(const float4*)&zs[r*68 + a0];
            float4 vb = *(const float4*)&zs[r*68 + b0];
            float av[4] = {va.x, va.y, va.z, va.w};
            float bv[4] = {vb.x, vb.y, vb.z, vb.w};
            #pragma unroll
            for (int i = 0; i < 4; i++)
                #pragma unroll
                for (int j = 0; j < 4; j++) acc[i][j] += av[i]*bv[j];
        }
    }
    __syncthreads();
    red[t] = csum;
    __syncthreads();
    if (t < 64) atomicAdd(&g_stats[256 + t], red[t] + red[64+t] + red[128+t] + red[192+t]);
    #pragma unroll
    for (int i = 0; i < 4; i++)
        #pragma unroll
        for (int j = 0; j < 4; j++)
            atomicAdd(&g_stats[320 + (a0+i)*64 + b0 + j], acc[i][j]);
}

// ---------------- analytic BN3: pack {sc,sh,w2} ----------------
__global__ void k_bn3fin(const float* __restrict__ W1, const float* __restrict__ b1,
                         const float* __restrict__ g3, const float* __restrict__ b3,
                         const float* __restrict__ W2) {
    __shared__ float Cov[EMB*EMB];
    __shared__ float zb[EMB];
    int t = threadIdx.x;
    for (int i = t; i < EMB; i += 32) zb[i] = g_stats[256+i] * (1.f/NT);
    __syncthreads();
    for (int i = t; i < EMB*EMB; i += 32)
        Cov[i] = g_stats[320+i] * (1.f/NT) - zb[i >> 6]*zb[i & 63];
    __syncthreads();
    int c = blockIdx.x*32 + t;
    const float* wc = W1 + c*EMB;
    float wr[EMB];
    #pragma unroll
    for (int k = 0; k < EMB; k++) wr[k] = wc[k];
    float m = b1[c];
    #pragma unroll
    for (int k = 0; k < EMB; k++) m += zb[k]*wr[k];
    float var = 0.f;
    for (int a = 0; a < EMB; a++) {
        float ta = 0.f;
        #pragma unroll 8
        for (int b = 0; b < EMB; b++) ta += Cov[a*EMB + b]*wr[b];
        var += ta * wr[a];
    }
    float sc = g3[c] * rsqrtf(var + EPS);
    g_abc[c] = make_float4(sc, b3[c] - m*sc, W2[c], 0.f);
}

// ---------------- final: split-N HMMA GEMM, A direct from gmem, atomic output ----------------
#define F2_BH  0
#define F2_BL  9216
#define F2_ABC 18432
#define SMEM_F2 ((18432 + 1024)*4)   /* 77824 B -> 2 CTAs/SM */

__global__ void __launch_bounds__(256, 2)
k_final_mma(const float* __restrict__ b2, float* __restrict__ out) {
    extern __shared__ uint32_t sm4[];
    uint32_t* Bh = sm4 + F2_BH;
    uint32_t* Bl = sm4 + F2_BL;
    float4*   abc = (float4*)(sm4 + F2_ABC);
    int t = threadIdx.x, lane = t & 31, wid = t >> 5;
    int g = lane >> 2, tid = lane & 3;
    int half = blockIdx.x & 1;
    const uint32_t* wh = g_W1h + half*256*32;
    const uint32_t* wl = g_W1l + half*256*32;
    for (int i = t; i < 256*32; i += 256) {
        int n = i >> 5, k2 = i & 31;
        Bh[n*36 + k2] = wh[i];
        Bl[n*36 + k2] = wl[i];
    }
    for (int i = t; i < 256; i += 256) abc[i] = g_abc[half*256 + i];
    float bb = half ? 0.f : b2[0];
    __syncthreads();

    int tstep = gridDim.x >> 1;
    for (int tile = blockIdx.x >> 1; tile < NT/128; tile += tstep) {
        int row = (tile << 7) + wid*16 + g;
        const uint4* zh0 = (const uint4*)(g_zrh + row*32);
        const uint4* zl0 = (const uint4*)(g_zrl + row*32);
        // row stride = 32 words = 8 uint4, so row+8 => +64 uint4
        uint4 qh0 = zh0[tid*2],      qh1 = zh0[tid*2 + 1];
        uint4 qh2 = zh0[tid*2 + 64], qh3 = zh0[tid*2 + 65];
        uint4 ql0 = zl0[tid*2],      ql1 = zl0[tid*2 + 1];
        uint4 ql2 = zl0[tid*2 + 64], ql3 = zl0[tid*2 + 65];
        uint32_t ah[4][4] = {
            {qh0.x, qh2.x, qh0.y, qh2.y}, {qh0.z, qh2.z, qh0.w, qh2.w},
            {qh1.x, qh3.x, qh1.y, qh3.y}, {qh1.z, qh3.z, qh1.w, qh3.w}};
        uint32_t al[4][4] = {
            {ql0.x, ql2.x, ql0.y, ql2.y}, {ql0.z, ql2.z, ql0.w, ql2.w},
            {ql1.x, ql3.x, ql1.y, ql3.y}, {ql1.z, ql3.z, ql1.w, ql3.w}};
        float part0 = 0.f, part1 = 0.f;
        #pragma unroll 4
        for (int nt = 0; nt < 32; nt++) {
            int nb = (nt*8 + g)*36 + tid*8;
            uint4 bh0 = *(const uint4*)&Bh[nb], bh1 = *(const uint4*)&Bh[nb+4];
            uint4 bl0 = *(const uint4*)&Bl[nb], bl1 = *(const uint4*)&Bl[nb+4];
            float hh[4]={0,0,0,0}, hl[4]={0,0,0,0}, lh[4]={0,0,0,0};
            mma16816(hh, ah[0], bh0.x, bh0.y); mma16816(hh, ah[1], bh0.z, bh0.w);
            mma16816(hh, ah[2], bh1.x, bh1.y); mma16816(hh, ah[3], bh1.z, bh1.w);
            mma16816(hl, ah[0], bl0.x, bl0.y); mma16816(hl, ah[1], bl0.z, bl0.w);
            mma16816(hl, ah[2], bl1.x, bl1.y); mma16816(hl, ah[3], bl1.z, bl1.w);
            mma16816(lh, al[0], bh0.x, bh0.y); mma16816(lh, al[1], bh0.z, bh0.w);
            mma16816(lh, al[2], bh1.x, bh1.y); mma16816(lh, al[3], bh1.z, bh1.w);
            float4 p0 = abc[nt*8 + tid*2];
            float4 p1 = abc[nt*8 + tid*2 + 1];
            float y;
            y = fmaxf(fmaf(hh[0]+hl[0]+lh[0], p0.x, p0.y), 0.f); part0 = fmaf(y, p0.z, part0);
            y = fmaxf(fmaf(hh[1]+hl[1]+lh[1], p1.x, p1.y), 0.f); part0 = fmaf(y, p1.z, part0);
            y = fmaxf(fmaf(hh[2]+hl[2]+lh[2], p0.x, p0.y), 0.f); part1 = fmaf(y, p0.z, part1);
            y = fmaxf(fmaf(hh[3]+hl[3]+lh[3], p1.x, p1.y), 0.f); part1 = fmaf(y, p1.z, part1);
        }
        part0 += __shfl_xor_sync(0xffffffffu, part0, 1);
        part0 += __shfl_xor_sync(0xffffffffu, part0, 2);
        part1 += __shfl_xor_sync(0xffffffffu, part1, 1);
        part1 += __shfl_xor_sync(0xffffffffu, part1, 2);
        if (tid == 0) {
            atomicAdd(&out[row],     part0 + bb);
            atomicAdd(&out[row + 8], part1 + bb);
        }
    }
}

// ---------------- launch ----------------
extern "C" void kernel_launch(void* const* d_in, const int* in_sizes, int n_in,
                              void* d_out, int out_size) {
    const float* data     = (const float*)d_in[0];
    const float* W_emb    = (const float*)d_in[2];
    const float* W_lin    = (const float*)d_in[3];
    const float* att_i    = (const float*)d_in[4];
    const float* att_j    = (const float*)d_in[5];
    const float* att_em_i = (const float*)d_in[6];
    const float* att_em_j = (const float*)d_in[7];
    const float* b_gnn    = (const float*)d_in[8];
    const float* gbn1     = (const float*)d_in[9];
    const float* bbn1     = (const float*)d_in[10];
    const float* gbn2     = (const float*)d_in[11];
    const float* bbn2     = (const float*)d_in[12];
    const float* W1       = (const float*)d_in[13];
    const float* b1       = (const float*)d_in[14];
    const float* gbn3     = (const float*)d_in[15];
    const float* bbn3     = (const float*)d_in[16];
    const float* W2       = (const float*)d_in[17];
    const float* b2       = (const float*)d_in[18];
    float* out = (float*)d_out;

    cudaFuncSetAttribute(k_xl_mma,    cudaFuncAttributeMaxDynamicSharedMemorySize, SMEM_XL);
    cudaFuncSetAttribute(k_agg,       cudaFuncAttributeMaxDynamicSharedMemorySize, SMEM_AGG);
    cudaFuncSetAttribute(k_final_mma, cudaFuncAttributeMaxDynamicSharedMemorySize, SMEM_F2);
    int nsm = 0;
    cudaDeviceGetAttribute(&nsm, cudaDevAttrMultiProcessorCount, 0);
    if (nsm <= 0) nsm = 148;

    k_prep<<<98, 512>>>(W_emb, att_em_i, att_em_j, W1, out);
    k_topk<<<64, 256>>>(W_emb);
    k_xl_mma<<<nsm*2, 256, SMEM_XL>>>(data, W_lin, att_i, att_j);
    k_agg<<<512, 256, SMEM_AGG>>>(b_gnn);
    k_hz2<<<1024, 256>>>(b_gnn, W_emb, gbn1, bbn1);
    k_zr<<<nsm*2, 256>>>(b_gnn, W_emb, gbn1, bbn1, gbn2, bbn2);
    k_bn3fin<<<16, 32>>>(W1, b1, gbn3, bbn3, W2);
    k_final_mma<<<nsm*2, 256, SMEM_F2>>>(b2, out);
}

// round 12
// speedup vs baseline: 1.7648x; 1.0250x over previous
#include <cuda_runtime.h>
#include <cuda_bf16.h>
#include <math.h>
#include <stdint.h>

#define BATCH 256
#define NODE  512
#define WIN   64
#define EMB   64
#define TOPK  16
#define INTER 512
#define NT    (BATCH*NODE)     /* 131072 */
#define NEG   0.2f
#define EPS   1e-5f

// ---------------- scratch (static device globals) ----------------
__device__ float g_xl[NT*EMB];
__device__ float g_agg[NT*EMB];
__device__ __align__(16) uint32_t g_zrh[NT*EMB/2];   // bf16x2, fragperm word order
__device__ __align__(16) uint32_t g_zrl[NT*EMB/2];
__device__ __align__(16) uint32_t g_W1h[INTER*EMB/2]; // fragperm word order
__device__ __align__(16) uint32_t g_W1l[INTER*EMB/2];
__device__ float g_si[NT];
__device__ float g_sj[NT];
__device__ int   g_topk[NODE*TOPK];
__device__ float g_ei[NODE], g_ej[NODE], g_inv[NODE];
// [0:64]=bn1 sum  [64:128]=bn1 sq  [128:192]=bn2 sum [192:256]=bn2 sq
// [256:320]=zr colsum  [320:4416]=M2 (64x64 second moment of zr)
__device__ float g_stats[4416];
__device__ float4 g_abc[INTER];   // {bn3_scale, bn3_shift, W2, 0}

// ---------------- HMMA helper ----------------
__device__ __forceinline__ void mma16816(float* d, const uint32_t* a, uint32_t b0, uint32_t b1) {
    asm volatile("mma.sync.aligned.m16n8k16.row.col.f32.bf16.bf16.f32 "
        "{%0,%1,%2,%3}, {%4,%5,%6,%7}, {%8,%9}, {%0,%1,%2,%3};"
        : "+f"(d[0]), "+f"(d[1]), "+f"(d[2]), "+f"(d[3])
        : "r"(a[0]), "r"(a[1]), "r"(a[2]), "r"(a[3]), "r"(b0), "r"(b1));
}
// fragment-order permutation of a 32-word (64 bf16) k-row
__device__ __forceinline__ int fragperm(int k2) {
    return (k2 & 3)*8 + (k2 >> 3)*2 + ((k2 >> 2) & 1);
}
__device__ __forceinline__ uint32_t packsplit(float x, float y, uint32_t* lo) {
    __nv_bfloat16 h0 = __float2bfloat16(x);
    __nv_bfloat16 h1 = __float2bfloat16(y);
    __nv_bfloat162 l2 = __halves2bfloat162(__float2bfloat16(x - __bfloat162float(h0)),
                                           __float2bfloat16(y - __bfloat162float(h1)));
    *lo = *(uint32_t*)&l2;
    __nv_bfloat162 h2 = __halves2bfloat162(h0, h1);
    return *(uint32_t*)&h2;
}

// ---------------- prep: zero stats + out; embed dots/norms; W1 hi/lo ----------------
__global__ void k_prep(const float* __restrict__ W_emb,
                       const float* __restrict__ aei,
                       const float* __restrict__ aej,
                       const float* __restrict__ W1,
                       float* __restrict__ out) {
    int t = threadIdx.x, b = blockIdx.x;
    if (b == 0) {
        for (int i = t; i < 4416; i += blockDim.x) g_stats[i] = 0.f;
    } else if (b == 1) {
        int v = t;
        const float* w = W_emb + v*EMB;
        float di = 0.f, dj = 0.f, nn = 0.f;
        #pragma unroll
        for (int k = 0; k < EMB; k++) {
            float x = w[k];
            di += x*aei[k]; dj += x*aej[k]; nn += x*x;
        }
        g_ei[v] = di; g_ej[v] = dj; g_inv[v] = rsqrtf(nn);
    } else if (b < 66) {
        float4* o4 = (float4*)out;
        int idx = (b - 2)*512 + t;              // 64 blocks * 512 threads = 32768 float4
        o4[idx] = make_float4(0.f, 0.f, 0.f, 0.f);
    } else {
        int i = (b - 66)*512 + t;               // 32 blocks: W1 split
        if (i < INTER*EMB/2) {
            float2 w = ((const float2*)W1)[i];
            uint32_t lo, hi = packsplit(w.x, w.y, &lo);
            int n = i >> 5, k2 = i & 31;
            int j = n*32 + fragperm(k2);
            g_W1h[j] = hi;
            g_W1l[j] = lo;
        }
    }
}

// ---------------- cosine-similarity top-k: one WARP per node, no barriers ----------------
__global__ void k_topk(const float* __restrict__ W_emb) {
    int t = threadIdx.x, lane = t & 31, w = t >> 5;
    int i = blockIdx.x*8 + w;   // node
    float wi[64];
    const float4* wi4 = (const float4*)&W_emb[i*64];
    #pragma unroll
    for (int k = 0; k < 16; k++) {
        float4 v = wi4[k];
        wi[k*4] = v.x; wi[k*4+1] = v.y; wi[k*4+2] = v.z; wi[k*4+3] = v.w;
    }
    float inv_i = g_inv[i];
    float cosv[16]; int jidx[16];
    #pragma unroll
    for (int q = 0; q < 16; q++) {
        int j = lane + q*32;
        const float4* wj = (const float4*)&W_emb[j*64];
        float d = 0.f;
        #pragma unroll
        for (int kk = 0; kk < 16; kk++) {
            float4 b = wj[kk];
            d += wi[kk*4]*b.x + wi[kk*4+1]*b.y + wi[kk*4+2]*b.z + wi[kk*4+3]*b.w;
        }
        cosv[q] = d * inv_i * g_inv[j];
        jidx[q] = j;
    }
    for (int s = 0; s < TOPK; s++) {
        float bv = -3e38f; int bj = NODE;
        #pragma unroll
        for (int q = 0; q < 16; q++) {
            if (cosv[q] > bv || (cosv[q] == bv && jidx[q] < bj)) { bv = cosv[q]; bj = jidx[q]; }
        }
        #pragma unroll
        for (int o = 16; o > 0; o >>= 1) {
            float v2 = __shfl_xor_sync(0xffffffffu, bv, o);
            int  j2 = __shfl_xor_sync(0xffffffffu, bj, o);
            if (v2 > bv || (v2 == bv && j2 < bj)) { bv = v2; bj = j2; }
        }
        if (lane == (bj & 31)) {
            int qi = bj >> 5;
            #pragma unroll
            for (int q = 0; q < 16; q++) if (q == qi) cosv[q] = -3e38f;
        }
        if (lane == 0) g_topk[i*TOPK + s] = bj;
    }
}

// ---------------- xl = x @ W_lin^T via HMMA split + fused attention scores ----------------
#define XL_BH 0
#define XL_BL 2304
#define XL_AH 4608
#define XL_AL 9216
#define XL_AI 13824
#define XL_AJ 13888
#define SMEM_XL (13952*4)
__global__ void __launch_bounds__(256, 2)
k_xl_mma(const float* __restrict__ x, const float* __restrict__ W_lin,
         const float* __restrict__ att_i, const float* __restrict__ att_j) {
    extern __shared__ uint32_t smx[];
    uint32_t* Bh = smx + XL_BH;
    uint32_t* Bl = smx + XL_BL;
    uint32_t* Ah = smx + XL_AH;
    uint32_t* Al = smx + XL_AL;
    float* ai = (float*)(smx + XL_AI);
    float* aj = (float*)(smx + XL_AJ);
    int t = threadIdx.x, lane = t & 31, wid = t >> 5;
    int g = lane >> 2, tid = lane & 3;
    for (int i = t; i < 64*32; i += 256) {
        int e = i >> 5, k2 = i & 31;
        float2 w = ((const float2*)W_lin)[i];
        uint32_t lo, hi = packsplit(w.x, w.y, &lo);
        int j = fragperm(k2);
        Bh[e*36 + j] = hi; Bl[e*36 + j] = lo;
    }
    if (t < 64) { ai[t] = att_i[t]; aj[t] = att_j[t]; }
    int r0 = wid*16 + g;
    for (int tile = blockIdx.x; tile < NT/128; tile += gridDim.x) {
        int row0 = tile << 7;
        __syncthreads();
        for (int i = t; i < 128*32; i += 256) {
            int r = i >> 5, k2 = i & 31;
            float2 v = ((const float2*)x)[row0*32 + i];
            uint32_t lo, hi = packsplit(v.x, v.y, &lo);
            int j = fragperm(k2);
            Ah[r*36 + j] = hi; Al[r*36 + j] = lo;
        }
        __syncthreads();
        uint4 qh0 = *(const uint4*)&Ah[r0*36 + tid*8];
        uint4 qh1 = *(const uint4*)&Ah[r0*36 + tid*8 + 4];
        uint4 qh2 = *(const uint4*)&Ah[(r0+8)*36 + tid*8];
        uint4 qh3 = *(const uint4*)&Ah[(r0+8)*36 + tid*8 + 4];
        uint4 ql0 = *(const uint4*)&Al[r0*36 + tid*8];
        uint4 ql1 = *(const uint4*)&Al[r0*36 + tid*8 + 4];
        uint4 ql2 = *(const uint4*)&Al[(r0+8)*36 + tid*8];
        uint4 ql3 = *(const uint4*)&Al[(r0+8)*36 + tid*8 + 4];
        uint32_t ah[4][4] = {
            {qh0.x, qh2.x, qh0.y, qh2.y}, {qh0.z, qh2.z, qh0.w, qh2.w},
            {qh1.x, qh3.x, qh1.y, qh3.y}, {qh1.z, qh3.z, qh1.w, qh3.w}};
        uint32_t al[4][4] = {
            {ql0.x, ql2.x, ql0.y, ql2.y}, {ql0.z, ql2.z, ql0.w, ql2.w},
            {ql1.x, ql3.x, ql1.y, ql3.y}, {ql1.z, ql3.z, ql1.w, ql3.w}};
        float pi0=0, pi1=0, pj0=0, pj1=0;
        #pragma unroll
        for (int nt = 0; nt < 8; nt++) {
            int nb = (nt*8 + g)*36 + tid*8;
            uint4 bh0 = *(const uint4*)&Bh[nb], bh1 = *(const uint4*)&Bh[nb+4];
            uint4 bl0 = *(const uint4*)&Bl[nb], bl1 = *(const uint4*)&Bl[nb+4];
            float hh[4]={0,0,0,0}, hl[4]={0,0,0,0}, lh[4]={0,0,0,0};
            mma16816(hh, ah[0], bh0.x, bh0.y); mma16816(hh, ah[1], bh0.z, bh0.w);
            mma16816(hh, ah[2], bh1.x, bh1.y); mma16816(hh, ah[3], bh1.z, bh1.w);
            mma16816(hl, ah[0], bl0.x, bl0.y); mma16816(hl, ah[1], bl0.z, bl0.w);
            mma16816(hl, ah[2], bl1.x, bl1.y); mma16816(hl, ah[3], bl1.z, bl1.w);
            mma16816(lh, al[0], bh0.x, bh0.y); mma16816(lh, al[1], bh0.z, bh0.w);
            mma16816(lh, al[2], bh1.x, bh1.y); mma16816(lh, al[3], bh1.z, bh1.w);
            float v0 = hh[0]+hl[0]+lh[0], v1 = hh[1]+hl[1]+lh[1];
            float v2 = hh[2]+hl[2]+lh[2], v3 = hh[3]+hl[3]+lh[3];
            int col = nt*8 + tid*2;
            *(float2*)&g_xl[(row0+r0)*64 + col]   = make_float2(v0, v1);
            *(float2*)&g_xl[(row0+r0+8)*64 + col] = make_float2(v2, v3);
            float a0 = ai[col], a1 = ai[col+1], j0 = aj[col], j1 = aj[col+1];
            pi0 += v0*a0 + v1*a1;  pj0 += v0*j0 + v1*j1;
            pi1 += v2*a0 + v3*a1;  pj1 += v2*j0 + v3*j1;
        }
        pi0 += __shfl_xor_sync(0xffffffffu, pi0, 1); pi0 += __shfl_xor_sync(0xffffffffu, pi0, 2);
        pj0 += __shfl_xor_sync(0xffffffffu, pj0, 1); pj0 += __shfl_xor_sync(0xffffffffu, pj0, 2);
        pi1 += __shfl_xor_sync(0xffffffffu, pi1, 1); pi1 += __shfl_xor_sync(0xffffffffu, pi1, 2);
        pj1 += __shfl_xor_sync(0xffffffffu, pj1, 1); pj1 += __shfl_xor_sync(0xffffffffu, pj1, 2);
        if (tid == 0) {
            int n0 = row0 + r0, v = n0 & (NODE-1);
            g_si[n0] = pi0 + g_ei[v]; g_sj[n0] = pj0 + g_ej[v];
            n0 += 8; v = n0 & (NODE-1);
            g_si[n0] = pi1 + g_ei[v]; g_sj[n0] = pj1 + g_ej[v];
        }
    }
}

// ---------------- GAT aggregation: one block per batch, full 64-ch slab, shfl broadcast ----------------
// smem floats: sxl[512*64]=32768, stk ints 8192 @32768, ssi @40960, ssj @41472,
//              sms @41984, smq @42048; total 42112 floats = 168448 B (1 CTA/SM)
#define SMEM_AGG (42112*4)
__global__ void __launch_bounds__(512, 1)
k_agg(const float* __restrict__ b_gnn) {
    extern __shared__ float smA[];
    float* sxl = smA;
    int*   stk = (int*)(smA + 32768);
    float* ssi = smA + 40960;
    float* ssj = smA + 41472;
    float* sms = smA + 41984;
    float* smq = smA + 42048;
    int t = threadIdx.x, wid = t >> 5, lane = t & 31;
    int b = blockIdx.x;
    const float4* src = (const float4*)&g_xl[b*NODE*EMB];
    float4* dst4 = (float4*)sxl;
    for (int i = t; i < 512*16; i += 512) dst4[i] = src[i];
    for (int i = t; i < NODE*TOPK; i += 512) stk[i] = g_topk[i];
    for (int i = t; i < NODE; i += 512) { ssi[i] = g_si[b*NODE + i]; ssj[i] = g_sj[b*NODE + i]; }
    if (t < 64) { sms[t] = 0.f; smq[t] = 0.f; }
    __syncthreads();
    int k = lane & 15;
    float2 bg = *(const float2*)&b_gnn[lane*2];
    const float2* sxl2 = (const float2*)sxl;
    float s0=0,q0=0,s1=0,q1=0;
    for (int v = wid*32; v < wid*32 + 32; v++) {
        int nbr = stk[v*16 + k];
        float a = ssi[v] + ssj[nbr];
        a = a > 0.f ? a : NEG*a;
        float m = a;
        #pragma unroll
        for (int o = 8; o > 0; o >>= 1) m = fmaxf(m, __shfl_xor_sync(0xffffffffu, m, o, 16));
        float ex = expf(a - m);
        float den = ex;
        #pragma unroll
        for (int o = 8; o > 0; o >>= 1) den += __shfl_xor_sync(0xffffffffu, den, o, 16);
        float w = ex / den;
        float ax = 0.f, ay = 0.f;
        #pragma unroll
        for (int kk = 0; kk < 16; kk++) {
            float wk = __shfl_sync(0xffffffffu, w,   kk, 16);
            int   nb = __shfl_sync(0xffffffffu, nbr, kk, 16);
            float2 vv = sxl2[nb*32 + lane];
            ax = fmaf(wk, vv.x, ax);
            ay = fmaf(wk, vv.y, ay);
        }
        *(float2*)&g_agg[(b*NODE + v)*EMB + lane*2] = make_float2(ax, ay);
        float z0 = ax + bg.x, z1 = ay + bg.y;
        s0 += z0; q0 += z0*z0; s1 += z1; q1 += z1*z1;
    }
    atomicAdd(&sms[lane*2],   s0); atomicAdd(&smq[lane*2],   q0);
    atomicAdd(&sms[lane*2+1], s1); atomicAdd(&smq[lane*2+1], q1);
    __syncthreads();
    if (t < 64) { atomicAdd(&g_stats[t], sms[t]); atomicAdd(&g_stats[64+t], smq[t]); }
}

// ---------------- bn2 stats from agg (bn1 finalized inline from g_stats) ----------------
__global__ void k_hz2(const float* __restrict__ b_gnn, const float* __restrict__ W_emb,
                      const float* __restrict__ g1, const float* __restrict__ b1v) {
    __shared__ float sA[64], sB[64], sm_s[64], sm_q[64];
    int t = threadIdx.x;
    if (t < 64) {
        float s = g_stats[t], q = g_stats[64+t];
        float m = s * (1.f/NT);
        float v = q * (1.f/NT) - m*m;
        float sc = g1[t] * rsqrtf(v + EPS);
        sA[t] = sc;
        sB[t] = fmaf(b_gnn[t], sc, b1v[t] - m*sc);
        sm_s[t] = 0.f; sm_q[t] = 0.f;
    }
    __syncthreads();
    int gt = blockIdx.x*256 + t;
    int c0 = (gt & 31)*2;
    float A0 = sA[c0], A1 = sA[c0+1];
    float B0 = sB[c0], B1 = sB[c0+1];
    float s0=0,q0=0,s1=0,q1=0;
    const float2* a2 = (const float2*)g_agg;
    const int stride = 1024*256;
    for (int idx = gt; idx < NT*32; idx += stride) {
        int row = idx >> 5;
        int v = row & (NODE-1);
        float2 a = a2[idx];
        float h0 = fmaxf(fmaf(a.x, A0, B0), 0.f);
        float h1 = fmaxf(fmaf(a.y, A1, B1), 0.f);
        float2 we = *(const float2*)&W_emb[v*EMB + c0];
        float z0 = h0 * we.x;
        float z1 = h1 * we.y;
        s0 += z0; q0 += z0*z0; s1 += z1; q1 += z1*z1;
    }
    atomicAdd(&sm_s[c0],   s0); atomicAdd(&sm_q[c0],   q0);
    atomicAdd(&sm_s[c0+1], s1); atomicAdd(&sm_q[c0+1], q1);
    __syncthreads();
    if (t < 64) { atomicAdd(&g_stats[128+t], sm_s[t]); atomicAdd(&g_stats[192+t], sm_q[t]); }
}

// ---------------- zr from agg (bn1+bn2 inline); emit bf16 hi/lo; SYRK + colsum ----------------
__global__ void __launch_bounds__(256, 2)
k_zr(const float* __restrict__ b_gnn, const float* __restrict__ W_emb,
     const float* __restrict__ g1, const float* __restrict__ b1v,
     const float* __restrict__ g2, const float* __restrict__ b2v) {
    __shared__ float zs[128*68];
    __shared__ float cA[64], cB[64], c2s[64], c2h[64];
    __shared__ float red[256];
    int t = threadIdx.x;
    if (t < 64) {
        float s = g_stats[t], q = g_stats[64+t];
        float m = s * (1.f/NT);
        float v = q * (1.f/NT) - m*m;
        float sc = g1[t] * rsqrtf(v + EPS);
        cA[t] = sc;
        cB[t] = fmaf(b_gnn[t], sc, b1v[t] - m*sc);
        s = g_stats[128+t]; q = g_stats[192+t];
        m = s * (1.f/NT);
        v = q * (1.f/NT) - m*m;
        sc = g2[t] * rsqrtf(v + EPS);
        c2s[t] = sc;
        c2h[t] = b2v[t] - m*sc;
    }
    int tx = t & 15, ty = t >> 4;
    int a0 = ty*4, b0 = tx*4;
    float acc[4][4];
    #pragma unroll
    for (int i = 0; i < 4; i++)
        #pragma unroll
        for (int j = 0; j < 4; j++) acc[i][j] = 0.f;
    float csum = 0.f;
    int cc = t & 63, rr0 = t >> 6;
    for (int tile = blockIdx.x; tile < NT/128; tile += gridDim.x) {
        int row0 = tile << 7;
        __syncthreads();
        for (int i = t; i < 128*32; i += 256) {
            int r = i >> 5, k2 = i & 31, c0 = k2*2;
            int v = (row0 + r) & (NODE-1);
            float2 a = ((const float2*)g_agg)[row0*32 + i];
            float2 we = *(const float2*)&W_emb[v*EMB + c0];
            float h0 = fmaxf(fmaf(a.x, cA[c0],   cB[c0]),   0.f);
            float h1 = fmaxf(fmaf(a.y, cA[c0+1], cB[c0+1]), 0.f);
            float z0 = fmaxf(fmaf(h0*we.x, c2s[c0],   c2h[c0]),   0.f);
            float z1 = fmaxf(fmaf(h1*we.y, c2s[c0+1], c2h[c0+1]), 0.f);
            zs[r*68 + c0] = z0; zs[r*68 + c0 + 1] = z1;
            uint32_t lo, hi = packsplit(z0, z1, &lo);
            int j = (row0 + r)*32 + fragperm(k2);
            g_zrh[j] = hi;
            g_zrl[j] = lo;
        }
        __syncthreads();
        for (int r = rr0; r < 128; r += 4) csum += zs[r*68 + cc];
        #pragma unroll 4
        for (int r = 0; r < 128; r++) {
            float4 va = *(const float4*)&zs[r*68 + a0];
            float4 vb = *(const float4*)&zs[r*68 + b0];
            float av[4] = {va.x, va.y, va.z, va.w};
            float bv[4] = {vb.x, vb.y, vb.z, vb.w};
            #pragma unroll
            for (int i = 0; i < 4; i++)
                #pragma unroll
                for (int j = 0; j < 4; j++) acc[i][j] += av[i]*bv[j];
        }
    }
    __syncthreads();
    red[t] = csum;
    __syncthreads();
    if (t < 64) atomicAdd(&g_stats[256 + t], red[t] + red[64+t] + red[128+t] + red[192+t]);
    #pragma unroll
    for (int i = 0; i < 4; i++)
        #pragma unroll
        for (int j = 0; j < 4; j++)
            atomicAdd(&g_stats[320 + (a0+i)*64 + b0 + j], acc[i][j]);
}

// ---------------- analytic BN3: pack {sc,sh,w2} ----------------
__global__ void k_bn3fin(const float* __restrict__ W1, const float* __restrict__ b1,
                         const float* __restrict__ g3, const float* __restrict__ b3,
                         const float* __restrict__ W2) {
    __shared__ float Cov[EMB*EMB];
    __shared__ float zb[EMB];
    int t = threadIdx.x;
    for (int i = t; i < EMB; i += 32) zb[i] = g_stats[256+i] * (1.f/NT);
    __syncthreads();
    for (int i = t; i < EMB*EMB; i += 32)
        Cov[i] = g_stats[320+i] * (1.f/NT) - zb[i >> 6]*zb[i & 63];
    __syncthreads();
    int c = blockIdx.x*32 + t;
    const float* wc = W1 + c*EMB;
    float wr[EMB];
    #pragma unroll
    for (int k = 0; k < EMB; k++) wr[k] = wc[k];
    float m = b1[c];
    #pragma unroll
    for (int k = 0; k < EMB; k++) m += zb[k]*wr[k];
    float var = 0.f;
    for (int a = 0; a < EMB; a++) {
        float ta = 0.f;
        #pragma unroll 8
        for (int b = 0; b < EMB; b++) ta += Cov[a*EMB + b]*wr[b];
        var += ta * wr[a];
    }
    float sc = g3[c] * rsqrtf(var + EPS);
    g_abc[c] = make_float4(sc, b3[c] - m*sc, W2[c], 0.f);
}

// ---------------- final: split-N HMMA GEMM, A direct from gmem, atomic output ----------------
#define F2_BH  0
#define F2_BL  9216
#define F2_ABC 18432
#define SMEM_F2 ((18432 + 1024)*4)   /* 77824 B -> 2 CTAs/SM */

__global__ void __launch_bounds__(256, 2)
k_final_mma(const float* __restrict__ b2, float* __restrict__ out) {
    extern __shared__ uint32_t sm4[];
    uint32_t* Bh = sm4 + F2_BH;
    uint32_t* Bl = sm4 + F2_BL;
    float4*   abc = (float4*)(sm4 + F2_ABC);
    int t = threadIdx.x, lane = t & 31, wid = t >> 5;
    int g = lane >> 2, tid = lane & 3;
    int half = blockIdx.x & 1;
    const uint32_t* wh = g_W1h + half*256*32;
    const uint32_t* wl = g_W1l + half*256*32;
    for (int i = t; i < 256*32; i += 256) {
        int n = i >> 5, k2 = i & 31;
        Bh[n*36 + k2] = wh[i];
        Bl[n*36 + k2] = wl[i];
    }
    for (int i = t; i < 256; i += 256) abc[i] = g_abc[half*256 + i];
    float bb = half ? 0.f : b2[0];
    __syncthreads();

    int tstep = gridDim.x >> 1;
    for (int tile = blockIdx.x >> 1; tile < NT/128; tile += tstep) {
        int row = (tile << 7) + wid*16 + g;
        const uint4* zh0 = (const uint4*)(g_zrh + row*32);
        const uint4* zl0 = (const uint4*)(g_zrl + row*32);
        // row stride = 32 words = 8 uint4, so row+8 => +64 uint4
        uint4 qh0 = zh0[tid*2],      qh1 = zh0[tid*2 + 1];
        uint4 qh2 = zh0[tid*2 + 64], qh3 = zh0[tid*2 + 65];
        uint4 ql0 = zl0[tid*2],      ql1 = zl0[tid*2 + 1];
        uint4 ql2 = zl0[tid*2 + 64], ql3 = zl0[tid*2 + 65];
        uint32_t ah[4][4] = {
            {qh0.x, qh2.x, qh0.y, qh2.y}, {qh0.z, qh2.z, qh0.w, qh2.w},
            {qh1.x, qh3.x, qh1.y, qh3.y}, {qh1.z, qh3.z, qh1.w, qh3.w}};
        uint32_t al[4][4] = {
            {ql0.x, ql2.x, ql0.y, ql2.y}, {ql0.z, ql2.z, ql0.w, ql2.w},
            {ql1.x, ql3.x, ql1.y, ql3.y}, {ql1.z, ql3.z, ql1.w, ql3.w}};
        float part0 = 0.f, part1 = 0.f;
        #pragma unroll 4
        for (int nt = 0; nt < 32; nt++) {
            int nb = (nt*8 + g)*36 + tid*8;
            uint4 bh0 = *(const uint4*)&Bh[nb], bh1 = *(const uint4*)&Bh[nb+4];
            uint4 bl0 = *(const uint4*)&Bl[nb], bl1 = *(const uint4*)&Bl[nb+4];
            float hh[4]={0,0,0,0}, hl[4]={0,0,0,0}, lh[4]={0,0,0,0};
            mma16816(hh, ah[0], bh0.x, bh0.y); mma16816(hh, ah[1], bh0.z, bh0.w);
            mma16816(hh, ah[2], bh1.x, bh1.y); mma16816(hh, ah[3], bh1.z, bh1.w);
            mma16816(hl, ah[0], bl0.x, bl0.y); mma16816(hl, ah[1], bl0.z, bl0.w);
            mma16816(hl, ah[2], bl1.x, bl1.y); mma16816(hl, ah[3], bl1.z, bl1.w);
            mma16816(lh, al[0], bh0.x, bh0.y); mma16816(lh, al[1], bh0.z, bh0.w);
            mma16816(lh, al[2], bh1.x, bh1.y); mma16816(lh, al[3], bh1.z, bh1.w);
            float4 p0 = abc[nt*8 + tid*2];
            float4 p1 = abc[nt*8 + tid*2 + 1];
            float y;
            y = fmaxf(fmaf(hh[0]+hl[0]+lh[0], p0.x, p0.y), 0.f); part0 = fmaf(y, p0.z, part0);
            y = fmaxf(fmaf(hh[1]+hl[1]+lh[1], p1.x, p1.y), 0.f); part0 = fmaf(y, p1.z, part0);
            y = fmaxf(fmaf(hh[2]+hl[2]+lh[2], p0.x, p0.y), 0.f); part1 = fmaf(y, p0.z, part1);
            y = fmaxf(fmaf(hh[3]+hl[3]+lh[3], p1.x, p1.y), 0.f); part1 = fmaf(y, p1.z, part1);
        }
        part0 += __shfl_xor_sync(0xffffffffu, part0, 1);
        part0 += __shfl_xor_sync(0xffffffffu, part0, 2);
        part1 += __shfl_xor_sync(0xffffffffu, part1, 1);
        part1 += __shfl_xor_sync(0xffffffffu, part1, 2);
        if (tid == 0) {
            atomicAdd(&out[row],     part0 + bb);
            atomicAdd(&out[row + 8], part1 + bb);
        }
    }
}

// ---------------- launch ----------------
extern "C" void kernel_launch(void* const* d_in, const int* in_sizes, int n_in,
                              void* d_out, int out_size) {
    const float* data     = (const float*)d_in[0];
    const float* W_emb    = (const float*)d_in[2];
    const float* W_lin    = (const float*)d_in[3];
    const float* att_i    = (const float*)d_in[4];
    const float* att_j    = (const float*)d_in[5];
    const float* att_em_i = (const float*)d_in[6];
    const float* att_em_j = (const float*)d_in[7];
    const float* b_gnn    = (const float*)d_in[8];
    const float* gbn1     = (const float*)d_in[9];
    const float* bbn1     = (const float*)d_in[10];
    const float* gbn2     = (const float*)d_in[11];
    const float* bbn2     = (const float*)d_in[12];
    const float* W1       = (const float*)d_in[13];
    const float* b1       = (const float*)d_in[14];
    const float* gbn3     = (const float*)d_in[15];
    const float* bbn3     = (const float*)d_in[16];
    const float* W2       = (const float*)d_in[17];
    const float* b2       = (const float*)d_in[18];
    float* out = (float*)d_out;

    cudaFuncSetAttribute(k_xl_mma,    cudaFuncAttributeMaxDynamicSharedMemorySize, SMEM_XL);
    cudaFuncSetAttribute(k_agg,       cudaFuncAttributeMaxDynamicSharedMemorySize, SMEM_AGG);
    cudaFuncSetAttribute(k_final_mma, cudaFuncAttributeMaxDynamicSharedMemorySize, SMEM_F2);
    int nsm = 0;
    cudaDeviceGetAttribute(&nsm, cudaDevAttrMultiProcessorCount, 0);
    if (nsm <= 0) nsm = 148;

    k_prep<<<98, 512>>>(W_emb, att_em_i, att_em_j, W1, out);
    k_topk<<<64, 256>>>(W_emb);
    k_xl_mma<<<nsm*2, 256, SMEM_XL>>>(data, W_lin, att_i, att_j);
    k_agg<<<BATCH, 512, SMEM_AGG>>>(b_gnn);
    k_hz2<<<1024, 256>>>(b_gnn, W_emb, gbn1, bbn1);
    k_zr<<<nsm*2, 256>>>(b_gnn, W_emb, gbn1, bbn1, gbn2, bbn2);
    k_bn3fin<<<16, 32>>>(W1, b1, gbn3, bbn3, W2);
    k_final_mma<<<nsm*2, 256, SMEM_F2>>>(b2, out);
}

// round 13
// speedup vs baseline: 1.8322x; 1.0382x over previous
#include <cuda_runtime.h>
#include <cuda_bf16.h>
#include <math.h>
#include <stdint.h>

#define BATCH 256
#define NODE  512
#define WIN   64
#define EMB   64
#define TOPK  16
#define INTER 512
#define NT    (BATCH*NODE)     /* 131072 */
#define NEG   0.2f
#define EPS   1e-5f

// ---------------- scratch (static device globals) ----------------
__device__ float g_xl[NT*EMB];
__device__ float g_agg[NT*EMB];
__device__ __align__(16) uint32_t g_zrh[NT*EMB/2];   // bf16x2, fragperm word order
__device__ __align__(16) uint32_t g_zrl[NT*EMB/2];
__device__ __align__(16) uint32_t g_W1h[INTER*EMB/2]; // fragperm word order
__device__ __align__(16) uint32_t g_W1l[INTER*EMB/2];
__device__ float g_si[NT];
__device__ float g_sj[NT];
__device__ int   g_topk[NODE*TOPK];
__device__ float g_ei[NODE], g_ej[NODE], g_inv[NODE];
// [0:64]=bn1 sum  [64:128]=bn1 sq  [128:192]=bn2 sum [192:256]=bn2 sq
// [256:320]=zr colsum  [320:4416]=M2 (64x64 second moment of zr)
__device__ float g_stats[4416];
__device__ float4 g_abc[INTER];   // {bn3_scale, bn3_shift, W2, 0}

// ---------------- HMMA helper ----------------
__device__ __forceinline__ void mma16816(float* d, const uint32_t* a, uint32_t b0, uint32_t b1) {
    asm volatile("mma.sync.aligned.m16n8k16.row.col.f32.bf16.bf16.f32 "
        "{%0,%1,%2,%3}, {%4,%5,%6,%7}, {%8,%9}, {%0,%1,%2,%3};"
        : "+f"(d[0]), "+f"(d[1]), "+f"(d[2]), "+f"(d[3])
        : "r"(a[0]), "r"(a[1]), "r"(a[2]), "r"(a[3]), "r"(b0), "r"(b1));
}
// fragment-order permutation of a 32-word (64 bf16) k-row
__device__ __forceinline__ int fragperm(int k2) {
    return (k2 & 3)*8 + (k2 >> 3)*2 + ((k2 >> 2) & 1);
}
__device__ __forceinline__ uint32_t packsplit(float x, float y, uint32_t* lo) {
    __nv_bfloat16 h0 = __float2bfloat16(x);
    __nv_bfloat16 h1 = __float2bfloat16(y);
    __nv_bfloat162 l2 = __halves2bfloat162(__float2bfloat16(x - __bfloat162float(h0)),
                                           __float2bfloat16(y - __bfloat162float(h1)));
    *lo = *(uint32_t*)&l2;
    __nv_bfloat162 h2 = __halves2bfloat162(h0, h1);
    return *(uint32_t*)&h2;
}

// ---------------- prep: zero stats + out; embed dots/norms; W1 hi/lo ----------------
__global__ void k_prep(const float* __restrict__ W_emb,
                       const float* __restrict__ aei,
                       const float* __restrict__ aej,
                       const float* __restrict__ W1,
                       float* __restrict__ out) {
    int t = threadIdx.x, b = blockIdx.x;
    if (b == 0) {
        for (int i = t; i < 4416; i += blockDim.x) g_stats[i] = 0.f;
    } else if (b == 1) {
        int v = t;
        const float* w = W_emb + v*EMB;
        float di = 0.f, dj = 0.f, nn = 0.f;
        #pragma unroll
        for (int k = 0; k < EMB; k++) {
            float x = w[k];
            di += x*aei[k]; dj += x*aej[k]; nn += x*x;
        }
        g_ei[v] = di; g_ej[v] = dj; g_inv[v] = rsqrtf(nn);
    } else if (b < 66) {
        float4* o4 = (float4*)out;
        int idx = (b - 2)*512 + t;              // 64 blocks * 512 threads = 32768 float4
        o4[idx] = make_float4(0.f, 0.f, 0.f, 0.f);
    } else {
        int i = (b - 66)*512 + t;               // 32 blocks: W1 split
        if (i < INTER*EMB/2) {
            float2 w = ((const float2*)W1)[i];
            uint32_t lo, hi = packsplit(w.x, w.y, &lo);
            int n = i >> 5, k2 = i & 31;
            int j = n*32 + fragperm(k2);
            g_W1h[j] = hi;
            g_W1l[j] = lo;
        }
    }
}

// ---------------- cosine-similarity top-k: one WARP per node, no barriers ----------------
__global__ void k_topk(const float* __restrict__ W_emb) {
    int t = threadIdx.x, lane = t & 31, w = t >> 5;
    int i = blockIdx.x*8 + w;   // node
    float wi[64];
    const float4* wi4 = (const float4*)&W_emb[i*64];
    #pragma unroll
    for (int k = 0; k < 16; k++) {
        float4 v = wi4[k];
        wi[k*4] = v.x; wi[k*4+1] = v.y; wi[k*4+2] = v.z; wi[k*4+3] = v.w;
    }
    float inv_i = g_inv[i];
    float cosv[16]; int jidx[16];
    #pragma unroll
    for (int q = 0; q < 16; q++) {
        int j = lane + q*32;
        const float4* wj = (const float4*)&W_emb[j*64];
        float d = 0.f;
        #pragma unroll
        for (int kk = 0; kk < 16; kk++) {
            float4 b = wj[kk];
            d += wi[kk*4]*b.x + wi[kk*4+1]*b.y + wi[kk*4+2]*b.z + wi[kk*4+3]*b.w;
        }
        cosv[q] = d * inv_i * g_inv[j];
        jidx[q] = j;
    }
    for (int s = 0; s < TOPK; s++) {
        float bv = -3e38f; int bj = NODE;
        #pragma unroll
        for (int q = 0; q < 16; q++) {
            if (cosv[q] > bv || (cosv[q] == bv && jidx[q] < bj)) { bv = cosv[q]; bj = jidx[q]; }
        }
        #pragma unroll
        for (int o = 16; o > 0; o >>= 1) {
            float v2 = __shfl_xor_sync(0xffffffffu, bv, o);
            int  j2 = __shfl_xor_sync(0xffffffffu, bj, o);
            if (v2 > bv || (v2 == bv && j2 < bj)) { bv = v2; bj = j2; }
        }
        if (lane == (bj & 31)) {
            int qi = bj >> 5;
            #pragma unroll
            for (int q = 0; q < 16; q++) if (q == qi) cosv[q] = -3e38f;
        }
        if (lane == 0) g_topk[i*TOPK + s] = bj;
    }
}

// ---------------- xl = x @ W_lin^T via HMMA split + fused attention scores ----------------
#define XL_BH 0
#define XL_BL 2304
#define XL_AH 4608
#define XL_AL 9216
#define XL_AI 13824
#define XL_AJ 13888
#define SMEM_XL (13952*4)
__global__ void __launch_bounds__(256, 2)
k_xl_mma(const float* __restrict__ x, const float* __restrict__ W_lin,
         const float* __restrict__ att_i, const float* __restrict__ att_j) {
    extern __shared__ uint32_t smx[];
    uint32_t* Bh = smx + XL_BH;
    uint32_t* Bl = smx + XL_BL;
    uint32_t* Ah = smx + XL_AH;
    uint32_t* Al = smx + XL_AL;
    float* ai = (float*)(smx + XL_AI);
    float* aj = (float*)(smx + XL_AJ);
    int t = threadIdx.x, lane = t & 31, wid = t >> 5;
    int g = lane >> 2, tid = lane & 3;
    for (int i = t; i < 64*32; i += 256) {
        int e = i >> 5, k2 = i & 31;
        float2 w = ((const float2*)W_lin)[i];
        uint32_t lo, hi = packsplit(w.x, w.y, &lo);
        int j = fragperm(k2);
        Bh[e*36 + j] = hi; Bl[e*36 + j] = lo;
    }
    if (t < 64) { ai[t] = att_i[t]; aj[t] = att_j[t]; }
    int r0 = wid*16 + g;
    for (int tile = blockIdx.x; tile < NT/128; tile += gridDim.x) {
        int row0 = tile << 7;
        __syncthreads();
        for (int i = t; i < 128*32; i += 256) {
            int r = i >> 5, k2 = i & 31;
            float2 v = ((const float2*)x)[row0*32 + i];
            uint32_t lo, hi = packsplit(v.x, v.y, &lo);
            int j = fragperm(k2);
            Ah[r*36 + j] = hi; Al[r*36 + j] = lo;
        }
        __syncthreads();
        uint4 qh0 = *(const uint4*)&Ah[r0*36 + tid*8];
        uint4 qh1 = *(const uint4*)&Ah[r0*36 + tid*8 + 4];
        uint4 qh2 = *(const uint4*)&Ah[(r0+8)*36 + tid*8];
        uint4 qh3 = *(const uint4*)&Ah[(r0+8)*36 + tid*8 + 4];
        uint4 ql0 = *(const uint4*)&Al[r0*36 + tid*8];
        uint4 ql1 = *(const uint4*)&Al[r0*36 + tid*8 + 4];
        uint4 ql2 = *(const uint4*)&Al[(r0+8)*36 + tid*8];
        uint4 ql3 = *(const uint4*)&Al[(r0+8)*36 + tid*8 + 4];
        uint32_t ah[4][4] = {
            {qh0.x, qh2.x, qh0.y, qh2.y}, {qh0.z, qh2.z, qh0.w, qh2.w},
            {qh1.x, qh3.x, qh1.y, qh3.y}, {qh1.z, qh3.z, qh1.w, qh3.w}};
        uint32_t al[4][4] = {
            {ql0.x, ql2.x, ql0.y, ql2.y}, {ql0.z, ql2.z, ql0.w, ql2.w},
            {ql1.x, ql3.x, ql1.y, ql3.y}, {ql1.z, ql3.z, ql1.w, ql3.w}};
        float pi0=0, pi1=0, pj0=0, pj1=0;
        #pragma unroll
        for (int nt = 0; nt < 8; nt++) {
            int nb = (nt*8 + g)*36 + tid*8;
            uint4 bh0 = *(const uint4*)&Bh[nb], bh1 = *(const uint4*)&Bh[nb+4];
            uint4 bl0 = *(const uint4*)&Bl[nb], bl1 = *(const uint4*)&Bl[nb+4];
            float hh[4]={0,0,0,0}, hl[4]={0,0,0,0}, lh[4]={0,0,0,0};
            mma16816(hh, ah[0], bh0.x, bh0.y); mma16816(hh, ah[1], bh0.z, bh0.w);
            mma16816(hh, ah[2], bh1.x, bh1.y); mma16816(hh, ah[3], bh1.z, bh1.w);
            mma16816(hl, ah[0], bl0.x, bl0.y); mma16816(hl, ah[1], bl0.z, bl0.w);
            mma16816(hl, ah[2], bl1.x, bl1.y); mma16816(hl, ah[3], bl1.z, bl1.w);
            mma16816(lh, al[0], bh0.x, bh0.y); mma16816(lh, al[1], bh0.z, bh0.w);
            mma16816(lh, al[2], bh1.x, bh1.y); mma16816(lh, al[3], bh1.z, bh1.w);
            float v0 = hh[0]+hl[0]+lh[0], v1 = hh[1]+hl[1]+lh[1];
            float v2 = hh[2]+hl[2]+lh[2], v3 = hh[3]+hl[3]+lh[3];
            int col = nt*8 + tid*2;
            *(float2*)&g_xl[(row0+r0)*64 + col]   = make_float2(v0, v1);
            *(float2*)&g_xl[(row0+r0+8)*64 + col] = make_float2(v2, v3);
            float a0 = ai[col], a1 = ai[col+1], j0 = aj[col], j1 = aj[col+1];
            pi0 += v0*a0 + v1*a1;  pj0 += v0*j0 + v1*j1;
            pi1 += v2*a0 + v3*a1;  pj1 += v2*j0 + v3*j1;
        }
        pi0 += __shfl_xor_sync(0xffffffffu, pi0, 1); pi0 += __shfl_xor_sync(0xffffffffu, pi0, 2);
        pj0 += __shfl_xor_sync(0xffffffffu, pj0, 1); pj0 += __shfl_xor_sync(0xffffffffu, pj0, 2);
        pi1 += __shfl_xor_sync(0xffffffffu, pi1, 1); pi1 += __shfl_xor_sync(0xffffffffu, pi1, 2);
        pj1 += __shfl_xor_sync(0xffffffffu, pj1, 1); pj1 += __shfl_xor_sync(0xffffffffu, pj1, 2);
        if (tid == 0) {
            int n0 = row0 + r0, v = n0 & (NODE-1);
            g_si[n0] = pi0 + g_ei[v]; g_sj[n0] = pj0 + g_ej[v];
            n0 += 8; v = n0 & (NODE-1);
            g_si[n0] = pi1 + g_ei[v]; g_sj[n0] = pj1 + g_ej[v];
        }
    }
}

// ---------------- GAT aggregation: 1024 threads, 2-node-per-warp softmax, shfl broadcast ----------------
// smem floats: sxl[512*64]=32768, stk ints 8192 @32768, ssi @40960, ssj @41472,
//              sms @41984, smq @42048; total 42112 floats = 168448 B (1 CTA/SM, 32 warps)
#define SMEM_AGG (42112*4)
__global__ void __launch_bounds__(1024, 1)
k_agg(const float* __restrict__ b_gnn) {
    extern __shared__ float smA[];
    float* sxl = smA;
    int*   stk = (int*)(smA + 32768);
    float* ssi = smA + 40960;
    float* ssj = smA + 41472;
    float* sms = smA + 41984;
    float* smq = smA + 42048;
    int t = threadIdx.x, wid = t >> 5, lane = t & 31;
    int b = blockIdx.x;
    const float4* src = (const float4*)&g_xl[b*NODE*EMB];
    float4* dst4 = (float4*)sxl;
    for (int i = t; i < 512*16; i += 1024) dst4[i] = src[i];
    for (int i = t; i < NODE*TOPK; i += 1024) stk[i] = g_topk[i];
    if (t < NODE) { ssi[t] = g_si[b*NODE + t]; ssj[t] = g_sj[b*NODE + t]; }
    if (t < 64) { sms[t] = 0.f; smq[t] = 0.f; }
    __syncthreads();
    int k = lane & 15, half = lane >> 4;
    float2 bg = *(const float2*)&b_gnn[lane*2];
    const float2* sxl2 = (const float2*)sxl;
    float s0=0,q0=0,s1=0,q1=0;
    int vbase = wid*16;       // 32 warps * 16 nodes = 512
    #pragma unroll 1
    for (int vp = 0; vp < 8; vp++) {
        // lanes 0-15 do softmax for node vA, lanes 16-31 for node vB
        int vA = vbase + vp*2;
        int v  = vA + half;
        int nbr = stk[v*16 + k];
        float a = ssi[v] + ssj[nbr];
        a = a > 0.f ? a : NEG*a;
        float m = a;
        #pragma unroll
        for (int o = 8; o > 0; o >>= 1) m = fmaxf(m, __shfl_xor_sync(0xffffffffu, m, o, 16));
        float ex = expf(a - m);
        float den = ex;
        #pragma unroll
        for (int o = 8; o > 0; o >>= 1) den += __shfl_xor_sync(0xffffffffu, den, o, 16);
        float w = ex / den;
        // gather node vA (weights live in lanes 0-15)
        float ax = 0.f, ay = 0.f;
        #pragma unroll
        for (int kk = 0; kk < 16; kk++) {
            float wk = __shfl_sync(0xffffffffu, w,   kk);
            int   nb = __shfl_sync(0xffffffffu, nbr, kk);
            float2 vv = sxl2[nb*32 + lane];
            ax = fmaf(wk, vv.x, ax);
            ay = fmaf(wk, vv.y, ay);
        }
        *(float2*)&g_agg[(b*NODE + vA)*EMB + lane*2] = make_float2(ax, ay);
        float z0 = ax + bg.x, z1 = ay + bg.y;
        s0 += z0; q0 += z0*z0; s1 += z1; q1 += z1*z1;
        // gather node vB (weights live in lanes 16-31)
        ax = 0.f; ay = 0.f;
        #pragma unroll
        for (int kk = 0; kk < 16; kk++) {
            float wk = __shfl_sync(0xffffffffu, w,   16 + kk);
            int   nb = __shfl_sync(0xffffffffu, nbr, 16 + kk);
            float2 vv = sxl2[nb*32 + lane];
            ax = fmaf(wk, vv.x, ax);
            ay = fmaf(wk, vv.y, ay);
        }
        *(float2*)&g_agg[(b*NODE + vA + 1)*EMB + lane*2] = make_float2(ax, ay);
        z0 = ax + bg.x; z1 = ay + bg.y;
        s0 += z0; q0 += z0*z0; s1 += z1; q1 += z1*z1;
    }
    atomicAdd(&sms[lane*2],   s0); atomicAdd(&smq[lane*2],   q0);
    atomicAdd(&sms[lane*2+1], s1); atomicAdd(&smq[lane*2+1], q1);
    __syncthreads();
    if (t < 64) { atomicAdd(&g_stats[t], sms[t]); atomicAdd(&g_stats[64+t], smq[t]); }
}

// ---------------- bn2 stats from agg (bn1 finalized inline from g_stats) ----------------
__global__ void k_hz2(const float* __restrict__ b_gnn, const float* __restrict__ W_emb,
                      const float* __restrict__ g1, const float* __restrict__ b1v) {
    __shared__ float sA[64], sB[64], sm_s[64], sm_q[64];
    int t = threadIdx.x;
    if (t < 64) {
        float s = g_stats[t], q = g_stats[64+t];
        float m = s * (1.f/NT);
        float v = q * (1.f/NT) - m*m;
        float sc = g1[t] * rsqrtf(v + EPS);
        sA[t] = sc;
        sB[t] = fmaf(b_gnn[t], sc, b1v[t] - m*sc);
        sm_s[t] = 0.f; sm_q[t] = 0.f;
    }
    __syncthreads();
    int gt = blockIdx.x*256 + t;
    int c0 = (gt & 31)*2;
    float A0 = sA[c0], A1 = sA[c0+1];
    float B0 = sB[c0], B1 = sB[c0+1];
    float s0=0,q0=0,s1=0,q1=0;
    const float2* a2 = (const float2*)g_agg;
    const int stride = 1024*256;
    for (int idx = gt; idx < NT*32; idx += stride) {
        int row = idx >> 5;
        int v = row & (NODE-1);
        float2 a = a2[idx];
        float h0 = fmaxf(fmaf(a.x, A0, B0), 0.f);
        float h1 = fmaxf(fmaf(a.y, A1, B1), 0.f);
        float2 we = *(const float2*)&W_emb[v*EMB + c0];
        float z0 = h0 * we.x;
        float z1 = h1 * we.y;
        s0 += z0; q0 += z0*z0; s1 += z1; q1 += z1*z1;
    }
    atomicAdd(&sm_s[c0],   s0); atomicAdd(&sm_q[c0],   q0);
    atomicAdd(&sm_s[c0+1], s1); atomicAdd(&sm_q[c0+1], q1);
    __syncthreads();
    if (t < 64) { atomicAdd(&g_stats[128+t], sm_s[t]); atomicAdd(&g_stats[192+t], sm_q[t]); }
}

// ---------------- zr from agg (bn1+bn2 inline); emit bf16 hi/lo; SYRK + colsum ----------------
__global__ void __launch_bounds__(256, 2)
k_zr(const float* __restrict__ b_gnn, const float* __restrict__ W_emb,
     const float* __restrict__ g1, const float* __restrict__ b1v,
     const float* __restrict__ g2, const float* __restrict__ b2v) {
    __shared__ float zs[128*68];
    __shared__ float cA[64], cB[64], c2s[64], c2h[64];
    __shared__ float red[256];
    int t = threadIdx.x;
    if (t < 64) {
        float s = g_stats[t], q = g_stats[64+t];
        float m = s * (1.f/NT);
        float v = q * (1.f/NT) - m*m;
        float sc = g1[t] * rsqrtf(v + EPS);
        cA[t] = sc;
        cB[t] = fmaf(b_gnn[t], sc, b1v[t] - m*sc);
        s = g_stats[128+t]; q = g_stats[192+t];
        m = s * (1.f/NT);
        v = q * (1.f/NT) - m*m;
        sc = g2[t] * rsqrtf(v + EPS);
        c2s[t] = sc;
        c2h[t] = b2v[t] - m*sc;
    }
    int tx = t & 15, ty = t >> 4;
    int a0 = ty*4, b0 = tx*4;
    float acc[4][4];
    #pragma unroll
    for (int i = 0; i < 4; i++)
        #pragma unroll
        for (int j = 0; j < 4; j++) acc[i][j] = 0.f;
    float csum = 0.f;
    int cc = t & 63, rr0 = t >> 6;
    for (int tile = blockIdx.x; tile < NT/128; tile += gridDim.x) {
        int row0 = tile << 7;
        __syncthreads();
        for (int i = t; i < 128*32; i += 256) {
            int r = i >> 5, k2 = i & 31, c0 = k2*2;
            int v = (row0 + r) & (NODE-1);
            float2 a = ((const float2*)g_agg)[row0*32 + i];
            float2 we = *(const float2*)&W_emb[v*EMB + c0];
            float h0 = fmaxf(fmaf(a.x, cA[c0],   cB[c0]),   0.f);
            float h1 = fmaxf(fmaf(a.y, cA[c0+1], cB[c0+1]), 0.f);
            float z0 = fmaxf(fmaf(h0*we.x, c2s[c0],   c2h[c0]),   0.f);
            float z1 = fmaxf(fmaf(h1*we.y, c2s[c0+1], c2h[c0+1]), 0.f);
            zs[r*68 + c0] = z0; zs[r*68 + c0 + 1] = z1;
            uint32_t lo, hi = packsplit(z0, z1, &lo);
            int j = (row0 + r)*32 + fragperm(k2);
            g_zrh[j] = hi;
            g_zrl[j] = lo;
        }
        __syncthreads();
        for (int r = rr0; r < 128; r += 4) csum += zs[r*68 + cc];
        #pragma unroll 4
        for (int r = 0; r < 128; r++) {
            float4 va = *(const float4*)&zs[r*68 + a0];
            float4 vb = *(const float4*)&zs[r*68 + b0];
            float av[4] = {va.x, va.y, va.z, va.w};
            float bv[4] = {vb.x, vb.y, vb.z, vb.w};
            #pragma unroll
            for (int i = 0; i < 4; i++)
                #pragma unroll
                for (int j = 0; j < 4; j++) acc[i][j] += av[i]*bv[j];
        }
    }
    __syncthreads();
    red[t] = csum;
    __syncthreads();
    if (t < 64) atomicAdd(&g_stats[256 + t], red[t] + red[64+t] + red[128+t] + red[192+t]);
    #pragma unroll
    for (int i = 0; i < 4; i++)
        #pragma unroll
        for (int j = 0; j < 4; j++)
            atomicAdd(&g_stats[320 + (a0+i)*64 + b0 + j], acc[i][j]);
}

// ---------------- analytic BN3: pack {sc,sh,w2} ----------------
__global__ void k_bn3fin(const float* __restrict__ W1, const float* __restrict__ b1,
                         const float* __restrict__ g3, const float* __restrict__ b3,
                         const float* __restrict__ W2) {
    __shared__ float Cov[EMB*EMB];
    __shared__ float zb[EMB];
    int t = threadIdx.x;
    for (int i = t; i < EMB; i += 32) zb[i] = g_stats[256+i] * (1.f/NT);
    __syncthreads();
    for (int i = t; i < EMB*EMB; i += 32)
        Cov[i] = g_stats[320+i] * (1.f/NT) - zb[i >> 6]*zb[i & 63];
    __syncthreads();
    int c = blockIdx.x*32 + t;
    const float* wc = W1 + c*EMB;
    float wr[EMB];
    #pragma unroll
    for (int k = 0; k < EMB; k++) wr[k] = wc[k];
    float m = b1[c];
    #pragma unroll
    for (int k = 0; k < EMB; k++) m += zb[k]*wr[k];
    float var = 0.f;
    for (int a = 0; a < EMB; a++) {
        float ta = 0.f;
        #pragma unroll 8
        for (int b = 0; b < EMB; b++) ta += Cov[a*EMB + b]*wr[b];
        var += ta * wr[a];
    }
    float sc = g3[c] * rsqrtf(var + EPS);
    g_abc[c] = make_float4(sc, b3[c] - m*sc, W2[c], 0.f);
}

// ---------------- final: split-N HMMA GEMM, A direct from gmem, atomic output ----------------
#define F2_BH  0
#define F2_BL  9216
#define F2_ABC 18432
#define SMEM_F2 ((18432 + 1024)*4)   /* 77824 B -> 2 CTAs/SM */

__global__ void __launch_bounds__(256, 2)
k_final_mma(const float* __restrict__ b2, float* __restrict__ out) {
    extern __shared__ uint32_t sm4[];
    uint32_t* Bh = sm4 + F2_BH;
    uint32_t* Bl = sm4 + F2_BL;
    float4*   abc = (float4*)(sm4 + F2_ABC);
    int t = threadIdx.x, lane = t & 31, wid = t >> 5;
    int g = lane >> 2, tid = lane & 3;
    int half = blockIdx.x & 1;
    const uint32_t* wh = g_W1h + half*256*32;
    const uint32_t* wl = g_W1l + half*256*32;
    for (int i = t; i < 256*32; i += 256) {
        int n = i >> 5, k2 = i & 31;
        Bh[n*36 + k2] = wh[i];
        Bl[n*36 + k2] = wl[i];
    }
    for (int i = t; i < 256; i += 256) abc[i] = g_abc[half*256 + i];
    float bb = half ? 0.f : b2[0];
    __syncthreads();

    int tstep = gridDim.x >> 1;
    for (int tile = blockIdx.x >> 1; tile < NT/128; tile += tstep) {
        int row = (tile << 7) + wid*16 + g;
        const uint4* zh0 = (const uint4*)(g_zrh + row*32);
        const uint4* zl0 = (const uint4*)(g_zrl + row*32);
        // row stride = 32 words = 8 uint4, so row+8 => +64 uint4
        uint4 qh0 = zh0[tid*2],      qh1 = zh0[tid*2 + 1];
        uint4 qh2 = zh0[tid*2 + 64], qh3 = zh0[tid*2 + 65];
        uint4 ql0 = zl0[tid*2],      ql1 = zl0[tid*2 + 1];
        uint4 ql2 = zl0[tid*2 + 64], ql3 = zl0[tid*2 + 65];
        uint32_t ah[4][4] = {
            {qh0.x, qh2.x, qh0.y, qh2.y}, {qh0.z, qh2.z, qh0.w, qh2.w},
            {qh1.x, qh3.x, qh1.y, qh3.y}, {qh1.z, qh3.z, qh1.w, qh3.w}};
        uint32_t al[4][4] = {
            {ql0.x, ql2.x, ql0.y, ql2.y}, {ql0.z, ql2.z, ql0.w, ql2.w},
            {ql1.x, ql3.x, ql1.y, ql3.y}, {ql1.z, ql3.z, ql1.w, ql3.w}};
        float part0 = 0.f, part1 = 0.f;
        #pragma unroll 4
        for (int nt = 0; nt < 32; nt++) {
            int nb = (nt*8 + g)*36 + tid*8;
            uint4 bh0 = *(const uint4*)&Bh[nb], bh1 = *(const uint4*)&Bh[nb+4];
            uint4 bl0 = *(const uint4*)&Bl[nb], bl1 = *(const uint4*)&Bl[nb+4];
            float hh[4]={0,0,0,0}, hl[4]={0,0,0,0}, lh[4]={0,0,0,0};
            mma16816(hh, ah[0], bh0.x, bh0.y); mma16816(hh, ah[1], bh0.z, bh0.w);
            mma16816(hh, ah[2], bh1.x, bh1.y); mma16816(hh, ah[3], bh1.z, bh1.w);
            mma16816(hl, ah[0], bl0.x, bl0.y); mma16816(hl, ah[1], bl0.z, bl0.w);
            mma16816(hl, ah[2], bl1.x, bl1.y); mma16816(hl, ah[3], bl1.z, bl1.w);
            mma16816(lh, al[0], bh0.x, bh0.y); mma16816(lh, al[1], bh0.z, bh0.w);
            mma16816(lh, al[2], bh1.x, bh1.y); mma16816(lh, al[3], bh1.z, bh1.w);
            float4 p0 = abc[nt*8 + tid*2];
            float4 p1 = abc[nt*8 + tid*2 + 1];
            float y;
            y = fmaxf(fmaf(hh[0]+hl[0]+lh[0], p0.x, p0.y), 0.f); part0 = fmaf(y, p0.z, part0);
            y = fmaxf(fmaf(hh[1]+hl[1]+lh[1], p1.x, p1.y), 0.f); part0 = fmaf(y, p1.z, part0);
            y = fmaxf(fmaf(hh[2]+hl[2]+lh[2], p0.x, p0.y), 0.f); part1 = fmaf(y, p0.z, part1);
            y = fmaxf(fmaf(hh[3]+hl[3]+lh[3], p1.x, p1.y), 0.f); part1 = fmaf(y, p1.z, part1);
        }
        part0 += __shfl_xor_sync(0xffffffffu, part0, 1);
        part0 += __shfl_xor_sync(0xffffffffu, part0, 2);
        part1 += __shfl_xor_sync(0xffffffffu, part1, 1);
        part1 += __shfl_xor_sync(0xffffffffu, part1, 2);
        if (tid == 0) {
            atomicAdd(&out[row],     part0 + bb);
            atomicAdd(&out[row + 8], part1 + bb);
        }
    }
}

// ---------------- launch ----------------
extern "C" void kernel_launch(void* const* d_in, const int* in_sizes, int n_in,
                              void* d_out, int out_size) {
    const float* data     = (const float*)d_in[0];
    const float* W_emb    = (const float*)d_in[2];
    const float* W_lin    = (const float*)d_in[3];
    const float* att_i    = (const float*)d_in[4];
    const float* att_j    = (const float*)d_in[5];
    const float* att_em_i = (const float*)d_in[6];
    const float* att_em_j = (const float*)d_in[7];
    const float* b_gnn    = (const float*)d_in[8];
    const float* gbn1     = (const float*)d_in[9];
    const float* bbn1     = (const float*)d_in[10];
    const float* gbn2     = (const float*)d_in[11];
    const float* bbn2     = (const float*)d_in[12];
    const float* W1       = (const float*)d_in[13];
    const float* b1       = (const float*)d_in[14];
    const float* gbn3     = (const float*)d_in[15];
    const float* bbn3     = (const float*)d_in[16];
    const float* W2       = (const float*)d_in[17];
    const float* b2       = (const float*)d_in[18];
    float* out = (float*)d_out;

    cudaFuncSetAttribute(k_xl_mma,    cudaFuncAttributeMaxDynamicSharedMemorySize, SMEM_XL);
    cudaFuncSetAttribute(k_agg,       cudaFuncAttributeMaxDynamicSharedMemorySize, SMEM_AGG);
    cudaFuncSetAttribute(k_final_mma, cudaFuncAttributeMaxDynamicSharedMemorySize, SMEM_F2);
    int nsm = 0;
    cudaDeviceGetAttribute(&nsm, cudaDevAttrMultiProcessorCount, 0);
    if (nsm <= 0) nsm = 148;

    k_prep<<<98, 512>>>(W_emb, att_em_i, att_em_j, W1, out);
    k_topk<<<64, 256>>>(W_emb);
    k_xl_mma<<<nsm*2, 256, SMEM_XL>>>(data, W_lin, att_i, att_j);
    k_agg<<<BATCH, 1024, SMEM_AGG>>>(b_gnn);
    k_hz2<<<1024, 256>>>(b_gnn, W_emb, gbn1, bbn1);
    k_zr<<<nsm*2, 256>>>(b_gnn, W_emb, gbn1, bbn1, gbn2, bbn2);
    k_bn3fin<<<16, 32>>>(W1, b1, gbn3, bbn3, W2);
    k_final_mma<<<nsm*2, 256, SMEM_F2>>>(b2, out);
}